// round 14
// baseline (speedup 1.0000x reference)
#include <cuda_runtime.h>
#include <cuda_fp16.h>
#include <math.h>
#include <stdint.h>

namespace {
constexpr int kB = 8, kN = 4096, kL = 8, kE = 16384, kH = 256;
constexpr int kV = 32000, kOV = 512, kMaxSteps = 6;
constexpr int kM = kB * kN;        // 32768
constexpr int k4H = 4 * kH;        // 1024
constexpr int kET = kB * kE;       // 131072 total edges
constexpr int TILE_A = 128 * 80;   // 10240 (32-K sub-tile, 128 rows)
constexpr int TILE_BB = 64 * 80;   // 5120  (32-K sub-tile, 64 rows)
constexpr int SUB_B = TILE_A + TILE_BB;      // 15360 per 32-K sub-tile pair
constexpr int STAGE64 = 2 * SUB_B;           // 30720 per 64-K stage
constexpr int GEMM_SMEM = 2 * STAGE64;       // 61440 -> 3 CTAs/SM (unchanged)
}

// ---------------- scratch ---------------------------------------------------
__device__ __half g_G0h[(size_t)kV * k4H];        // embed @ Wi0, fp16, gate-permuted
__device__ __half g_c0[kM * kH], g_c1[kM * kH];
__device__ __half g_h0h[2][kM * kH];
__device__ __half g_h1h[2][kM * kH];              // buffer 0 doubles as se fp16
__device__ float g_se[kM * kH];
__device__ __half g_embh[(size_t)kV * kH];
__device__ __half g_Wi0T[k4H * kH], g_Wh0T[k4H * kH];
__device__ __half g_Wi1T[k4H * kH], g_Wh1T[k4H * kH];
__device__ __half g_WkT[kH * kH];
__device__ float g_bP0[k4H], g_bP1[k4H];
__device__ __half g_keysh[kM * kH];
__device__ float g_ak[kM], g_aq[kM];
__device__ float g_ae[8];
// CSR by destination node (built once per launch; topology is static)
__device__ int g_cnt[kM], g_cur[kM], g_off[kM + 1], g_eidx[kET];

// ---------------- PTX helpers ----------------------------------------------
__device__ __forceinline__ uint32_t smem_u32(const void* p) {
    uint32_t a;
    asm("{ .reg .u64 t; cvta.to.shared.u64 t, %1; cvt.u32.u64 %0, t; }"
        : "=r"(a) : "l"(p));
    return a;
}
__device__ __forceinline__ void cpasync16(uint32_t dst, const void* src) {
    asm volatile("cp.async.cg.shared.global [%0], [%1], 16;"
                 :: "r"(dst), "l"(src) : "memory");
}
__device__ __forceinline__ void cp_commit() {
    asm volatile("cp.async.commit_group;" ::: "memory");
}
template <int N>
__device__ __forceinline__ void cp_wait() {
    asm volatile("cp.async.wait_group %0;" :: "n"(N) : "memory");
}
__device__ __forceinline__ void ldsm4(uint32_t* r, uint32_t a) {
    asm volatile("ldmatrix.sync.aligned.m8n8.x4.shared.b16 {%0,%1,%2,%3}, [%4];"
                 : "=r"(r[0]), "=r"(r[1]), "=r"(r[2]), "=r"(r[3]) : "r"(a));
}
__device__ __forceinline__ void mma16816(float* d, const uint32_t* a, const uint32_t* b) {
    asm volatile(
        "mma.sync.aligned.m16n8k16.row.col.f32.f16.f16.f32 "
        "{%0,%1,%2,%3}, {%4,%5,%6,%7}, {%8,%9}, {%0,%1,%2,%3};"
        : "+f"(d[0]), "+f"(d[1]), "+f"(d[2]), "+f"(d[3])
        : "r"(a[0]), "r"(a[1]), "r"(a[2]), "r"(a[3]), "r"(b[0]), "r"(b[1]));
}
__device__ __forceinline__ float sigm(float x) { return 1.f / (1.f + expf(-x)); }

// ---------------- shared GEMM mainloop pieces --------------------------------
// CTA tile 128(M) x 64(N). K-chunk 64 = two 32-K sub-tiles per stage; 2 stages.
// 8 warps: warp tile 32x32.
#define GEMM_PROLOGUE                                                            \
    extern __shared__ __align__(128) char smem[];                               \
    const int tid = threadIdx.x, wid = tid >> 5, lane = tid & 31;               \
    const int mBase = blockIdx.y * 128, nBase = blockIdx.x * 64;                \
    const int wM = (wid & 3) * 32, wN = (wid >> 2) * 32;                        \
    const uint32_t sbase = smem_u32(smem);                                      \
    float acc[2][4][4];                                                         \
    _Pragma("unroll") for (int i = 0; i < 2; i++)                               \
    _Pragma("unroll") for (int j = 0; j < 4; j++)                               \
    _Pragma("unroll") for (int k = 0; k < 4; k++) acc[i][j][k] = 0.f;

// load one 32-K sub-tile pair (A 128x32, B 64x32) at sub-offset
__device__ __forceinline__ void load_sub(uint32_t subBase, int tid,
        const __half* __restrict__ Ap, const __half* __restrict__ Bp,
        int mBase, int nBase, int kt) {
    const uint32_t sA = subBase;
    const uint32_t sB = subBase + TILE_A;
#pragma unroll
    for (int i = 0; i < 2; i++) {
        int idx = i * 256 + tid;
        int r = idx >> 2, c4 = idx & 3;
        cpasync16(sA + r * 80 + c4 * 16,
                  Ap + (size_t)(mBase + r) * 256 + kt + c4 * 8);
    }
    {
        int r = tid >> 2, c4 = tid & 3;
        cpasync16(sB + r * 80 + c4 * 16,
                  Bp + (size_t)(nBase + r) * 256 + kt + c4 * 8);
    }
}

// load a full 64-K stage (two sub-tiles), single commit group
__device__ __forceinline__ void load_stage(uint32_t sbase, int buf, int tid,
        const __half* __restrict__ Ap, const __half* __restrict__ Bp,
        int mBase, int nBase, int kt) {
    uint32_t st = sbase + (uint32_t)buf * STAGE64;
    load_sub(st,         tid, Ap, Bp, mBase, nBase, kt);
    load_sub(st + SUB_B, tid, Ap, Bp, mBase, nBase, kt + 32);
    cp_commit();
}

// compute one 32-K sub-tile pair
__device__ __forceinline__ void compute_sub(uint32_t subBase,
        int wM, int wN, int lane, float acc[2][4][4]) {
    const uint32_t sA = subBase;
    const uint32_t sB = subBase + TILE_A;
#pragma unroll
    for (int ks = 0; ks < 2; ks++) {
        uint32_t a[2][4];
#pragma unroll
        for (int mt = 0; mt < 2; mt++) {
            int row = wM + mt * 16 + (lane & 15);
            ldsm4(a[mt], sA + row * 80 + ((lane >> 4) * 16) + ks * 32);
        }
#pragma unroll
        for (int nt2 = 0; nt2 < 2; nt2++) {
            uint32_t b[4];
            int nrow = wN + nt2 * 16 + (lane & 7) + ((lane >> 4) << 3);
            ldsm4(b, sB + nrow * 80 + (((lane >> 3) & 1) * 16) + ks * 32);
            mma16816(acc[0][nt2 * 2 + 0], a[0], b + 0);
            mma16816(acc[0][nt2 * 2 + 1], a[0], b + 2);
            mma16816(acc[1][nt2 * 2 + 0], a[1], b + 0);
            mma16816(acc[1][nt2 * 2 + 1], a[1], b + 2);
        }
    }
}

__device__ __forceinline__ void compute_stage(uint32_t sbase, int buf,
        int wM, int wN, int lane, float acc[2][4][4]) {
    uint32_t st = sbase + (uint32_t)buf * STAGE64;
    compute_sub(st,         wM, wN, lane, acc);
    compute_sub(st + SUB_B, wM, wN, lane, acc);
}

// 2-stage pipeline over 64-K chunks: one wait+sync per 64-K chunk.
// SRCS(c, Ap, Bp, kt) yields sources for 64-K chunk c (kt in {0,64,128,192}).
#define GEMM_MAINLOOP64(NCHUNKS, SRCS)                                           \
    {                                                                             \
        const __half *Ap_, *Bp_; int kt_;                                         \
        SRCS(0, Ap_, Bp_, kt_);                                                   \
        load_stage(sbase, 0, tid, Ap_, Bp_, mBase, nBase, kt_);                   \
        for (int c = 0; c < (NCHUNKS); ++c) {                                    \
            cp_wait<0>();                                                         \
            __syncthreads();                                                      \
            if (c + 1 < (NCHUNKS)) {                                              \
                SRCS(c + 1, Ap_, Bp_, kt_);                                       \
                load_stage(sbase, (c + 1) & 1, tid, Ap_, Bp_,                     \
                           mBase, nBase, kt_);                                    \
            }                                                                     \
            compute_stage(sbase, c & 1, wM, wN, lane, acc);                       \
        }                                                                         \
    }

// ---------------- generic 1-pass fp16 GEMM (G0 precompute, keys) -------------
__global__ void __launch_bounds__(256, 3) mma_gemm(
    int M, int NTotal,
    const __half* __restrict__ A, const __half* __restrict__ B,
    const float* __restrict__ bias, float* __restrict__ C,
    __half* __restrict__ Ch,
    const int* __restrict__ steps, int step, const float* __restrict__ Wa)
{
    if (steps && step >= steps[(blockIdx.y * 128) / kN]) return;
    GEMM_PROLOGUE
#define SRCS_PLAIN(c, Ap, Bp, kt) { Ap = A; Bp = B; kt = (c) * 64; }
    GEMM_MAINLOOP64(4, SRCS_PLAIN)
#undef SRCS_PLAIN

#pragma unroll
    for (int mt = 0; mt < 2; mt++) {
        int r0 = mBase + wM + mt * 16 + (lane >> 2);
        int r1 = r0 + 8;
        float ak0 = 0.f, aq0 = 0.f, ak1 = 0.f, aq1 = 0.f;
#pragma unroll
        for (int nt = 0; nt < 4; nt++) {
            int n = nBase + wN + nt * 8 + (lane & 3) * 2;
            float2 v0 = make_float2(acc[mt][nt][0], acc[mt][nt][1]);
            float2 v1 = make_float2(acc[mt][nt][2], acc[mt][nt][3]);
            if (bias) {
                float2 bv = *(const float2*)(bias + n);
                v0.x += bv.x; v0.y += bv.y; v1.x += bv.x; v1.y += bv.y;
            }
            if (Ch) {
                *(__half2*)(Ch + (size_t)r0 * NTotal + n) =
                    __halves2half2(__float2half(v0.x), __float2half(v0.y));
                *(__half2*)(Ch + (size_t)r1 * NTotal + n) =
                    __halves2half2(__float2half(v1.x), __float2half(v1.y));
            }
            if (C) {
                *(float2*)(C + (size_t)r0 * NTotal + n) = v0;
                *(float2*)(C + (size_t)r1 * NTotal + n) = v1;
            }
            if (Wa) {
                float2 w1 = *(const float2*)(Wa + n);
                float2 w2 = *(const float2*)(Wa + kH + n);
                ak0 += v0.x * w1.x + v0.y * w1.y;
                aq0 += v0.x * w2.x + v0.y * w2.y;
                ak1 += v1.x * w1.x + v1.y * w1.y;
                aq1 += v1.x * w2.x + v1.y * w2.y;
            }
        }
        if (Wa) {
#pragma unroll
            for (int o = 1; o <= 2; o <<= 1) {
                ak0 += __shfl_xor_sync(0xffffffffu, ak0, o);
                aq0 += __shfl_xor_sync(0xffffffffu, aq0, o);
                ak1 += __shfl_xor_sync(0xffffffffu, ak1, o);
                aq1 += __shfl_xor_sync(0xffffffffu, aq1, o);
            }
            if ((lane & 3) == 0) {
                atomicAdd(&g_ak[r0], ak0);
                atomicAdd(&g_aq[r0], aq0);
                atomicAdd(&g_ak[r1], ak1);
                atomicAdd(&g_aq[r1], aq1);
            }
        }
    }
}

// ---------------- fused LSTM GEMM + gates (1-pass fp16) -----------------------
struct LstmParams {
    int nPairs;
    const __half* A0; const __half* B0;
    const __half* A1; const __half* B1;
    const float* biasP;
    const __half* G0h; const int* tokIdx; int tokStride;
    __half* c; __half* outh; float* seOut;
};

__device__ __forceinline__ void lstm_body(const LstmParams& P)
{
    GEMM_PROLOGUE
    const int nChunks = P.nPairs * 4;
#define SRCS_LSTM(cc, Ap, Bp, kt) { int pair_ = (cc) >> 2;                      \
        kt = ((cc) & 3) * 64;                                                    \
        Ap = pair_ ? P.A1 : P.A0; Bp = pair_ ? P.B1 : P.B0; }
    GEMM_MAINLOOP64(nChunks, SRCS_LSTM)
#undef SRCS_LSTM

#pragma unroll
    for (int mt = 0; mt < 2; mt++) {
        int r0 = mBase + wM + mt * 16 + (lane >> 2);
        int r1 = r0 + 8;
        const __half *g0 = nullptr, *g1 = nullptr;
        if (P.G0h) {
            g0 = P.G0h + (size_t)P.tokIdx[(size_t)r0 * P.tokStride] * k4H;
            g1 = P.G0h + (size_t)P.tokIdx[(size_t)r1 * P.tokStride] * k4H;
        }
#pragma unroll
        for (int nt = 0; nt < 4; nt++) {
            int n = nBase + wN + nt * 8 + (lane & 3) * 2;
            float z0 = acc[mt][nt][0] + P.biasP[n];
            float z1 = acc[mt][nt][1] + P.biasP[n + 1];
            float z2 = acc[mt][nt][2] + P.biasP[n];
            float z3 = acc[mt][nt][3] + P.biasP[n + 1];
            if (g0) {
                __half2 a0 = *(const __half2*)(g0 + n);
                __half2 a1 = *(const __half2*)(g1 + n);
                z0 += __half2float(a0.x); z1 += __half2float(a0.y);
                z2 += __half2float(a1.x); z3 += __half2float(a1.y);
            }
            float e0 = __shfl_xor_sync(0xffffffffu, z0, 1);
            float e1 = __shfl_xor_sync(0xffffffffu, z1, 1);
            float e2 = __shfl_xor_sync(0xffffffffu, z2, 1);
            float e3 = __shfl_xor_sync(0xffffffffu, z3, 1);
            bool evn = (lane & 1) == 0;
            int row = evn ? r0 : r1;
            float zi = evn ? z0 : e2;
            float zf = evn ? z1 : e3;
            float zg = evn ? e0 : z2;
            float zo = evn ? e1 : z3;
            int uG = ((nBase + wN + nt * 8) >> 2) + ((lane & 3) >> 1);
            size_t idx = (size_t)row * kH + uG;
            float cn = sigm(zf) * __half2float(P.c[idx]) + sigm(zi) * tanhf(zg);
            P.c[idx] = __float2half(cn);
            float hn = sigm(zo) * tanhf(cn);
            P.outh[idx] = __float2half(hn);
            if (P.seOut) P.seOut[idx] = hn;
        }
    }
}

__global__ void __launch_bounds__(256, 3) mma_lstm1(LstmParams pa)
{
    lstm_body(pa);
}
// merged wavefront: z=0 runs layer1(t), z=1 runs layer0(t+1) — independent
__global__ void __launch_bounds__(256, 3) mma_lstm2(LstmParams pa, LstmParams pb)
{
    lstm_body(blockIdx.z ? pb : pa);
}

// ---------------- t=0 layer-0 special case: h0=0 -> z = G0[token] + bias ------
__global__ void __launch_bounds__(256) lstm0_init_kernel(
    const int* __restrict__ tokIdx, int tokStride,
    const __half* __restrict__ G0h, const float* __restrict__ bP0,
    __half* __restrict__ c, __half* __restrict__ outh)
{
    int idx = blockIdx.x * 256 + threadIdx.x;     // m*kH + u
    int m = idx >> 8, u = idx & 255;
    int tok = tokIdx[(size_t)m * tokStride];
    const __half2* g = (const __half2*)(G0h + (size_t)tok * k4H + u * 4);
    __half2 ga = g[0], gb = g[1];
    const float4 bv = *(const float4*)(bP0 + u * 4);
    float zi = __half2float(ga.x) + bv.x;
    float zg = __half2float(gb.x) + bv.z;
    float zo = __half2float(gb.y) + bv.w;
    float cn = sigm(zi) * tanhf(zg);              // f-term vanishes (c=0)
    c[idx] = __float2half(cn);
    outh[idx] = __float2half(sigm(zo) * tanhf(cn));
}

// ---------------- consolidated weight prep ------------------------------------
__global__ void __launch_bounds__(256) prep_weights_kernel(
    const float* __restrict__ Wi0, const float* __restrict__ Wh0,
    const float* __restrict__ Wi1, const float* __restrict__ Wh1,
    const float* __restrict__ Wk,
    const float* __restrict__ b0, const float* __restrict__ b1,
    __half* __restrict__ Wi0T, __half* __restrict__ Wh0T,
    __half* __restrict__ Wi1T, __half* __restrict__ Wh1T,
    __half* __restrict__ WkT, float* __restrict__ bP0, float* __restrict__ bP1)
{
    int blk = blockIdx.x;
    if (blk < 512) {
        const float* W; __half* T;
        switch (blk >> 7) {
            case 0: W = Wi0; T = Wi0T; break;
            case 1: W = Wh0; T = Wh0T; break;
            case 2: W = Wi1; T = Wi1T; break;
            default: W = Wh1; T = Wh1T;
        }
        int n = (blk & 127) * 8 + (threadIdx.x >> 5);
        int lane = threadIdx.x & 31;
        int col = (n & 3) * kH + (n >> 2);
        for (int kk = lane; kk < kH; kk += 32)
            T[(size_t)n * kH + kk] = __float2half(W[(size_t)kk * k4H + col]);
    } else if (blk < 544) {
        int n = (blk - 512) * 8 + (threadIdx.x >> 5);
        int lane = threadIdx.x & 31;
        for (int kk = lane; kk < kH; kk += 32)
            WkT[(size_t)n * kH + kk] = __float2half(Wk[(size_t)kk * kH + n]);
    } else {
        int i = blk - 544;                       // 0..7
        const float* b = (i < 4) ? b0 : b1;
        float* bP = (i < 4) ? bP0 : bP1;
        int n = (i & 3) * 256 + threadIdx.x;
        bP[n] = b[(n & 3) * kH + (n >> 2)];
    }
}

__global__ void __launch_bounds__(256) convert_embed_kernel(
    const float4* __restrict__ x, __half2* __restrict__ h2, int n4)
{
    int i = blockIdx.x * 256 + threadIdx.x;
    if (i >= n4) return;
    float4 v = x[i];
    h2[i * 2 + 0] = __halves2half2(__float2half(v.x), __float2half(v.y));
    h2[i * 2 + 1] = __halves2half2(__float2half(v.z), __float2half(v.w));
}

// ---------------- CSR build (once per launch; topology static) ----------------
__global__ void csr_zero_kernel()
{
    int i = blockIdx.x * 256 + threadIdx.x;
    g_cnt[i] = 0;
    g_cur[i] = 0;
}
__global__ void csr_count_kernel(const int* __restrict__ dst)
{
    int e = blockIdx.x * 256 + threadIdx.x;
    int node = (e / kE) * kN + dst[e];
    atomicAdd(&g_cnt[node], 1);
}
__global__ void __launch_bounds__(1024) csr_scan_kernel()
{
    __shared__ int sh[1024];
    __shared__ int carry;
    int tid = threadIdx.x;
    if (tid == 0) carry = 0;
    __syncthreads();
    for (int chunk = 0; chunk < kM / 1024; chunk++) {
        int i = chunk * 1024 + tid;
        int v = g_cnt[i];
        sh[tid] = v;
        __syncthreads();
        for (int o = 1; o < 1024; o <<= 1) {
            int t = (tid >= o) ? sh[tid - o] : 0;
            __syncthreads();
            sh[tid] += t;
            __syncthreads();
        }
        g_off[i] = carry + sh[tid] - v;     // exclusive
        __syncthreads();
        if (tid == 1023) carry += sh[1023];
        __syncthreads();
    }
    if (tid == 0) g_off[kM] = carry;
}
__global__ void csr_scatter_kernel(const int* __restrict__ dst)
{
    int e = blockIdx.x * 256 + threadIdx.x;
    int node = (e / kE) * kN + dst[e];
    int pos = g_off[node] + atomicAdd(&g_cur[node], 1);
    g_eidx[pos] = e;
}

// ---------------- GAT helpers -------------------------------------------------
__global__ void compute_ae_kernel(const float* __restrict__ edge_table,
                                  const float* __restrict__ Wa)
{
    int w = threadIdx.x >> 5, lane = threadIdx.x & 31;
    if (w >= 6) return;
    float s = 0.f;
    for (int hh = lane; hh < kH; hh += 32) s += edge_table[w * kH + hh] * Wa[hh];
#pragma unroll
    for (int o = 16; o; o >>= 1) s += __shfl_down_sync(0xffffffffu, s, o);
    if (!lane) g_ae[w] = s;
}

__global__ void init_akaq_kernel()
{
    int i = blockIdx.x * 256 + threadIdx.x;
    g_ak[i] = 0.f;
    g_aq[i] = 0.f;
}

// gather with fused edge scoring: one warp per dst node.
__global__ void __launch_bounds__(256) node_gather_kernel(
    const int* __restrict__ src, const int* __restrict__ et,
    const int* __restrict__ steps, int step, const float* __restrict__ ba,
    const float* __restrict__ edge_table,
    const __half* __restrict__ keysh,
    float* __restrict__ se, __half* __restrict__ seh)
{
    int node = blockIdx.x * 8 + (threadIdx.x >> 5);
    int lane = threadIdx.x & 31;
    int b = node / kN;
    if (step >= steps[b]) return;
    int lo = g_off[node], hi = g_off[node + 1];
    float acc[8] = {0, 0, 0, 0, 0, 0, 0, 0};
    float sum_ex = 0.f;
    int base = b * kN;
    float aq_ba = g_aq[node] + ba[0];
    for (int i = lo; i < hi; i++) {
        int e = g_eidx[i];
        int s = src[e], t = et[e];
        float lg = g_ak[base + s] + g_ae[t] + aq_ba;
        lg = fmaxf(0.2f * lg, lg);
        float ex = expf(lg);
        sum_ex += ex;
        const __half2* kr = (const __half2*)(keysh + (size_t)(base + s) * kH + lane * 8);
        const float4* er = (const float4*)(edge_table + t * kH + lane * 8);
        __half2 k0 = kr[0], k1 = kr[1], k2 = kr[2], k3 = kr[3];
        float4 e0 = er[0], e1 = er[1];
        acc[0] += (__half2float(k0.x) + e0.x) * ex;
        acc[1] += (__half2float(k0.y) + e0.y) * ex;
        acc[2] += (__half2float(k1.x) + e0.z) * ex;
        acc[3] += (__half2float(k1.y) + e0.w) * ex;
        acc[4] += (__half2float(k2.x) + e1.x) * ex;
        acc[5] += (__half2float(k2.y) + e1.y) * ex;
        acc[6] += (__half2float(k3.x) + e1.z) * ex;
        acc[7] += (__half2float(k3.y) + e1.w) * ex;
    }
    float inv = (hi > lo) ? (1.f / sum_ex) : 0.f;
    float4 o0, o1;
    o0.x = acc[0] * inv; o0.y = acc[1] * inv; o0.z = acc[2] * inv; o0.w = acc[3] * inv;
    o1.x = acc[4] * inv; o1.y = acc[5] * inv; o1.z = acc[6] * inv; o1.w = acc[7] * inv;
    float4* srow = (float4*)(se + (size_t)node * kH + lane * 8);
    srow[0] = o0;
    srow[1] = o1;
    __half2* hrow = (__half2*)(seh + (size_t)node * kH + lane * 8);
    hrow[0] = __halves2half2(__float2half(o0.x), __float2half(o0.y));
    hrow[1] = __halves2half2(__float2half(o0.z), __float2half(o0.w));
    hrow[2] = __halves2half2(__float2half(o1.x), __float2half(o1.y));
    hrow[3] = __halves2half2(__float2half(o1.z), __float2half(o1.w));
}

// ---------------- final gather + dense ---------------------------------------
__global__ void __launch_bounds__(256) final_kernel(
    const float* __restrict__ se, const int* __restrict__ exit_index,
    const float* __restrict__ Wo, const float* __restrict__ bo,
    float* __restrict__ out)
{
    __shared__ float fin[kH];
    int b = blockIdx.x, tid = threadIdx.x;
    const float* row = se + ((size_t)b * kN + exit_index[b]) * kH;
    if (tid < kH) fin[tid] = row[tid];
    __syncthreads();
    for (int j = tid; j < kOV; j += 256) {
        float s = bo[j];
        for (int hh = 0; hh < kH; hh++) s += fin[hh] * Wo[(size_t)hh * kOV + j];
        out[b * kOV + j] = s;
    }
}

// ---------------- driver ------------------------------------------------------
extern "C" void kernel_launch(void* const* d_in, const int* in_sizes, int n_in,
                              void* d_out, int out_size)
{
    const int*   data       = (const int*)d_in[0];
    const int*   src        = (const int*)d_in[1];
    const int*   dst        = (const int*)d_in[2];
    const int*   et         = (const int*)d_in[3];
    const int*   steps      = (const int*)d_in[4];
    const int*   exit_index = (const int*)d_in[5];
    const float* embed      = (const float*)d_in[6];
    const float* Wi0        = (const float*)d_in[7];
    const float* Wh0        = (const float*)d_in[8];
    const float* b0         = (const float*)d_in[9];
    const float* Wi1        = (const float*)d_in[10];
    const float* Wh1        = (const float*)d_in[11];
    const float* b1         = (const float*)d_in[12];
    const float* Wk         = (const float*)d_in[13];
    const float* bk         = (const float*)d_in[14];
    const float* Wa         = (const float*)d_in[15];
    const float* ba         = (const float*)d_in[16];
    const float* edge_table = (const float*)d_in[17];
    const float* Wo         = (const float*)d_in[18];
    const float* bo         = (const float*)d_in[19];
    float* out = (float*)d_out;

    float *se, *bP0, *bP1;
    __half *G0h, *c0, *c1, *h0h, *h1h, *embh, *keysh;
    __half *Wi0T, *Wh0T, *Wi1T, *Wh1T, *WkT;
    cudaGetSymbolAddress((void**)&G0h,   g_G0h);
    cudaGetSymbolAddress((void**)&c0,    g_c0);
    cudaGetSymbolAddress((void**)&c1,    g_c1);
    cudaGetSymbolAddress((void**)&se,    g_se);
    cudaGetSymbolAddress((void**)&keysh, g_keysh);
    cudaGetSymbolAddress((void**)&h0h,   g_h0h);
    cudaGetSymbolAddress((void**)&h1h,   g_h1h);
    cudaGetSymbolAddress((void**)&embh,  g_embh);
    cudaGetSymbolAddress((void**)&Wi0T,  g_Wi0T);
    cudaGetSymbolAddress((void**)&Wh0T,  g_Wh0T);
    cudaGetSymbolAddress((void**)&Wi1T,  g_Wi1T);
    cudaGetSymbolAddress((void**)&Wh1T,  g_Wh1T);
    cudaGetSymbolAddress((void**)&WkT,   g_WkT);
    cudaGetSymbolAddress((void**)&bP0,   g_bP0);
    cudaGetSymbolAddress((void**)&bP1,   g_bP1);

    cudaFuncSetAttribute(mma_gemm, cudaFuncAttributeMaxDynamicSharedMemorySize, GEMM_SMEM);
    cudaFuncSetAttribute(mma_lstm1, cudaFuncAttributeMaxDynamicSharedMemorySize, GEMM_SMEM);
    cudaFuncSetAttribute(mma_lstm2, cudaFuncAttributeMaxDynamicSharedMemorySize, GEMM_SMEM);

    const size_t hElems = (size_t)kM * kH;
    cudaMemsetAsync(c1, 0, hElems * 2);   // L1(0) epilogue reads c1

    prep_weights_kernel<<<552, 256>>>(Wi0, Wh0, Wi1, Wh1, Wk, b0, b1,
                                      Wi0T, Wh0T, Wi1T, Wh1T, WkT, bP0, bP1);
    convert_embed_kernel<<<(kV * kH / 4 + 255) / 256, 256>>>(
        (const float4*)embed, (__half2*)embh, kV * kH / 4);

    // CSR build (static topology: once per launch)
    csr_zero_kernel<<<kM / 256, 256>>>();
    csr_count_kernel<<<kET / 256, 256>>>(dst);
    csr_scan_kernel<<<1, 1024>>>();
    csr_scatter_kernel<<<kET / 256, 256>>>(dst);

    // G0 = embed @ Wi0 (gate-permuted, fp16)  [32000, 1024]
    mma_gemm<<<dim3(k4H / 64, kV / 128), 256, GEMM_SMEM>>>(
        kV, k4H, embh, Wi0T, nullptr, nullptr, G0h, nullptr, 0, nullptr);

    // ---- LSTM wavefront ----
    auto L0 = [&](int t) {
        LstmParams p{};
        p.nPairs = 1;
        p.A0 = h0h + (size_t)(t & 1) * hElems;  p.B0 = Wh0T;
        p.biasP = bP0;
        p.G0h = G0h; p.tokIdx = data + t; p.tokStride = kL;
        p.c = c0;
        p.outh = h0h + (size_t)((t & 1) ^ 1) * hElems;
        p.seOut = nullptr;
        return p;
    };
    auto L1 = [&](int t) {
        LstmParams p{};
        p.nPairs = 2;
        p.A0 = h0h + (size_t)((t & 1) ^ 1) * hElems;  p.B0 = Wi1T;  // h0(t)
        p.A1 = h1h + (size_t)(t & 1) * hElems;        p.B1 = Wh1T;
        p.biasP = bP1;
        p.c = c1;
        p.outh = h1h + (size_t)((t & 1) ^ 1) * hElems;
        p.seOut = (t == kL - 1) ? se : nullptr;
        return p;
    };
    // t=0, layer 0: GEMM is zero (h0=0) -> pure gather+gates; writes buffer 1
    lstm0_init_kernel<<<kM * kH / 256, 256>>>(data, kL, G0h, bP0,
                                              c0, h0h + hElems);
    {   // t=0, layer 1: h1=0 -> drop the Wh1 pair; merged with L0(1)
        LstmParams l10 = L1(0);
        l10.nPairs = 1;
        mma_lstm2<<<dim3(k4H / 64, kM / 128, 2), 256, GEMM_SMEM>>>(l10, L0(1));
    }
    for (int t = 1; t < kL - 1; t++)
        mma_lstm2<<<dim3(k4H / 64, kM / 128, 2), 256, GEMM_SMEM>>>(L1(t), L0(t + 1));
    mma_lstm1<<<dim3(k4H / 64, kM / 128), 256, GEMM_SMEM>>>(L1(kL - 1));
    // final h1 fp16 in buffer 0 (t=7 writes wb=0); se fp32 also written

    compute_ae_kernel<<<1, 256>>>(edge_table, Wa);

    for (int step = 0; step < kMaxSteps; step++) {
        init_akaq_kernel<<<kM / 256, 256>>>();
        // keys (fp16) = se @ Wk + bk, with fused partial ak/aq dots
        mma_gemm<<<dim3(kH / 64, kM / 128), 256, GEMM_SMEM>>>(
            kM, kH, h1h, WkT, bk, nullptr, keysh, steps, step, Wa);
        node_gather_kernel<<<kM / 8, 256>>>(src, et, steps, step, ba,
                                            edge_table, keysh, se, h1h);
        // h1h (buffer 0) now holds updated se fp16 for next keys GEMM
    }

    final_kernel<<<kB, 256>>>(se, exit_index, Wo, bo, out);
}

// round 15
// speedup vs baseline: 1.0440x; 1.0440x over previous
#include <cuda_runtime.h>
#include <cuda_fp16.h>
#include <math.h>
#include <stdint.h>

namespace {
constexpr int kB = 8, kN = 4096, kL = 8, kE = 16384, kH = 256;
constexpr int kV = 32000, kOV = 512, kMaxSteps = 6;
constexpr int kM = kB * kN;        // 32768
constexpr int k4H = 4 * kH;        // 1024
constexpr int kET = kB * kE;       // 131072 total edges
constexpr int STAGES = 4;
constexpr int TILE_A = 128 * 80;   // 10240
constexpr int TILE_BB = 64 * 80;   // 5120
constexpr int STAGE_B = TILE_A + TILE_BB;              // 15360
constexpr int GEMM_SMEM = STAGES * STAGE_B;            // 61440 -> 3 CTAs/SM
}

// ---------------- scratch ---------------------------------------------------
__device__ __half g_G0h[(size_t)kV * k4H];        // embed @ Wi0, fp16, gate-permuted
__device__ __half g_c0[kM * kH], g_c1[kM * kH];
__device__ __half g_h0h[2][kM * kH];
__device__ __half g_h1h[2][kM * kH];              // buffer 0 = se fp16 (live state)
__device__ __half g_embh[(size_t)kV * kH];
__device__ __half g_Wi0T[k4H * kH], g_Wh0T[k4H * kH];
__device__ __half g_Wi1T[k4H * kH], g_Wh1T[k4H * kH];
__device__ __half g_WkT[kH * kH];
__device__ float g_bP0[k4H], g_bP1[k4H];
__device__ __half g_keysh[kM * kH];
__device__ float g_ak[kM], g_aq[kM];
__device__ float g_ae[8];
// CSR by destination node (built once per launch; topology is static)
__device__ int g_cnt[kM], g_cur[kM], g_off[kM + 1], g_eidx[kET];

// ---------------- PTX helpers ----------------------------------------------
__device__ __forceinline__ uint32_t smem_u32(const void* p) {
    uint32_t a;
    asm("{ .reg .u64 t; cvta.to.shared.u64 t, %1; cvt.u32.u64 %0, t; }"
        : "=r"(a) : "l"(p));
    return a;
}
__device__ __forceinline__ void cpasync16(uint32_t dst, const void* src) {
    asm volatile("cp.async.cg.shared.global [%0], [%1], 16;"
                 :: "r"(dst), "l"(src) : "memory");
}
__device__ __forceinline__ void cp_commit() {
    asm volatile("cp.async.commit_group;" ::: "memory");
}
template <int N>
__device__ __forceinline__ void cp_wait() {
    asm volatile("cp.async.wait_group %0;" :: "n"(N) : "memory");
}
__device__ __forceinline__ void ldsm4(uint32_t* r, uint32_t a) {
    asm volatile("ldmatrix.sync.aligned.m8n8.x4.shared.b16 {%0,%1,%2,%3}, [%4];"
                 : "=r"(r[0]), "=r"(r[1]), "=r"(r[2]), "=r"(r[3]) : "r"(a));
}
__device__ __forceinline__ void mma16816(float* d, const uint32_t* a, const uint32_t* b) {
    asm volatile(
        "mma.sync.aligned.m16n8k16.row.col.f32.f16.f16.f32 "
        "{%0,%1,%2,%3}, {%4,%5,%6,%7}, {%8,%9}, {%0,%1,%2,%3};"
        : "+f"(d[0]), "+f"(d[1]), "+f"(d[2]), "+f"(d[3])
        : "r"(a[0]), "r"(a[1]), "r"(a[2]), "r"(a[3]), "r"(b[0]), "r"(b[1]));
}
__device__ __forceinline__ float sigm(float x) { return 1.f / (1.f + expf(-x)); }

// ---------------- shared GEMM mainloop pieces --------------------------------
// CTA tile 128(M) x 64(N), K-chunk 32, 4 stages (round-13 proven config).
#define GEMM_PROLOGUE                                                            \
    extern __shared__ __align__(128) char smem[];                               \
    const int tid = threadIdx.x, wid = tid >> 5, lane = tid & 31;               \
    const int mBase = blockIdx.y * 128, nBase = blockIdx.x * 64;                \
    const int wM = (wid & 3) * 32, wN = (wid >> 2) * 32;                        \
    const uint32_t sbase = smem_u32(smem);                                      \
    float acc[2][4][4];                                                         \
    _Pragma("unroll") for (int i = 0; i < 2; i++)                               \
    _Pragma("unroll") for (int j = 0; j < 4; j++)                               \
    _Pragma("unroll") for (int k = 0; k < 4; k++) acc[i][j][k] = 0.f;

__device__ __forceinline__ void load_tiles(uint32_t sbase, int buf, int tid,
        const __half* __restrict__ Ap, const __half* __restrict__ Bp,
        int mBase, int nBase, int kt) {
    const uint32_t sA = sbase + (uint32_t)buf * STAGE_B;
    const uint32_t sB = sA + TILE_A;
#pragma unroll
    for (int i = 0; i < 2; i++) {
        int idx = i * 256 + tid;
        int r = idx >> 2, c4 = idx & 3;
        cpasync16(sA + r * 80 + c4 * 16,
                  Ap + (size_t)(mBase + r) * 256 + kt + c4 * 8);
    }
    {
        int r = tid >> 2, c4 = tid & 3;
        cpasync16(sB + r * 80 + c4 * 16,
                  Bp + (size_t)(nBase + r) * 256 + kt + c4 * 8);
    }
    cp_commit();
}

__device__ __forceinline__ void compute_tiles(uint32_t sbase, int buf,
        int wM, int wN, int lane, float acc[2][4][4]) {
    const uint32_t sA = sbase + (uint32_t)buf * STAGE_B;
    const uint32_t sB = sA + TILE_A;
#pragma unroll
    for (int ks = 0; ks < 2; ks++) {
        uint32_t a[2][4], b[2][4];
        // hoist all ldsm ahead of the mma burst (wider ldsm->mma distance)
#pragma unroll
        for (int mt = 0; mt < 2; mt++) {
            int row = wM + mt * 16 + (lane & 15);
            ldsm4(a[mt], sA + row * 80 + ((lane >> 4) * 16) + ks * 32);
        }
#pragma unroll
        for (int nt2 = 0; nt2 < 2; nt2++) {
            int nrow = wN + nt2 * 16 + (lane & 7) + ((lane >> 4) << 3);
            ldsm4(b[nt2], sB + nrow * 80 + (((lane >> 3) & 1) * 16) + ks * 32);
        }
#pragma unroll
        for (int nt2 = 0; nt2 < 2; nt2++) {
            mma16816(acc[0][nt2 * 2 + 0], a[0], b[nt2] + 0);
            mma16816(acc[0][nt2 * 2 + 1], a[0], b[nt2] + 2);
            mma16816(acc[1][nt2 * 2 + 0], a[1], b[nt2] + 0);
            mma16816(acc[1][nt2 * 2 + 1], a[1], b[nt2] + 2);
        }
    }
}

#define GEMM_MAINLOOP(NCHUNKS, SRCS)                                            \
    {                                                                            \
        const __half *Ap_, *Bp_; int kt_;                                        \
        _Pragma("unroll") for (int s = 0; s < STAGES - 1; s++) {                 \
            if (s < (NCHUNKS)) { SRCS(s, Ap_, Bp_, kt_);                         \
                load_tiles(sbase, s, tid, Ap_, Bp_, mBase, nBase, kt_); }        \
            else cp_commit();                                                    \
        }                                                                        \
        for (int c = 0; c < (NCHUNKS); ++c) {                                   \
            cp_wait<STAGES - 2>();                                               \
            __syncthreads();                                                     \
            int pre = c + STAGES - 1;                                            \
            if (pre < (NCHUNKS)) { SRCS(pre, Ap_, Bp_, kt_);                     \
                load_tiles(sbase, pre & (STAGES - 1), tid, Ap_, Bp_,             \
                           mBase, nBase, kt_); }                                 \
            else cp_commit();                                                    \
            compute_tiles(sbase, c & (STAGES - 1), wM, wN, lane, acc);           \
        }                                                                        \
    }

// ---------------- generic 1-pass fp16 GEMM (G0 precompute, keys) -------------
__global__ void __launch_bounds__(256, 3) mma_gemm(
    int M, int NTotal,
    const __half* __restrict__ A, const __half* __restrict__ B,
    const float* __restrict__ bias, float* __restrict__ C,
    __half* __restrict__ Ch,
    const int* __restrict__ steps, int step, const float* __restrict__ Wa)
{
    if (steps && step >= steps[(blockIdx.y * 128) / kN]) return;
    GEMM_PROLOGUE
#define SRCS_PLAIN(c, Ap, Bp, kt) { Ap = A; Bp = B; kt = (c) * 32; }
    GEMM_MAINLOOP(8, SRCS_PLAIN)
#undef SRCS_PLAIN

#pragma unroll
    for (int mt = 0; mt < 2; mt++) {
        int r0 = mBase + wM + mt * 16 + (lane >> 2);
        int r1 = r0 + 8;
        float ak0 = 0.f, aq0 = 0.f, ak1 = 0.f, aq1 = 0.f;
#pragma unroll
        for (int nt = 0; nt < 4; nt++) {
            int n = nBase + wN + nt * 8 + (lane & 3) * 2;
            float2 v0 = make_float2(acc[mt][nt][0], acc[mt][nt][1]);
            float2 v1 = make_float2(acc[mt][nt][2], acc[mt][nt][3]);
            if (bias) {
                float2 bv = *(const float2*)(bias + n);
                v0.x += bv.x; v0.y += bv.y; v1.x += bv.x; v1.y += bv.y;
            }
            if (Ch) {
                *(__half2*)(Ch + (size_t)r0 * NTotal + n) =
                    __halves2half2(__float2half(v0.x), __float2half(v0.y));
                *(__half2*)(Ch + (size_t)r1 * NTotal + n) =
                    __halves2half2(__float2half(v1.x), __float2half(v1.y));
            }
            if (C) {
                *(float2*)(C + (size_t)r0 * NTotal + n) = v0;
                *(float2*)(C + (size_t)r1 * NTotal + n) = v1;
            }
            if (Wa) {
                float2 w1 = *(const float2*)(Wa + n);
                float2 w2 = *(const float2*)(Wa + kH + n);
                ak0 += v0.x * w1.x + v0.y * w1.y;
                aq0 += v0.x * w2.x + v0.y * w2.y;
                ak1 += v1.x * w1.x + v1.y * w1.y;
                aq1 += v1.x * w2.x + v1.y * w2.y;
            }
        }
        if (Wa) {
#pragma unroll
            for (int o = 1; o <= 2; o <<= 1) {
                ak0 += __shfl_xor_sync(0xffffffffu, ak0, o);
                aq0 += __shfl_xor_sync(0xffffffffu, aq0, o);
                ak1 += __shfl_xor_sync(0xffffffffu, ak1, o);
                aq1 += __shfl_xor_sync(0xffffffffu, aq1, o);
            }
            if ((lane & 3) == 0) {
                atomicAdd(&g_ak[r0], ak0);
                atomicAdd(&g_aq[r0], aq0);
                atomicAdd(&g_ak[r1], ak1);
                atomicAdd(&g_aq[r1], aq1);
            }
        }
    }
}

// ---------------- fused LSTM GEMM + gates (1-pass fp16) -----------------------
struct LstmParams {
    int nPairs;
    const __half* A0; const __half* B0;
    const __half* A1; const __half* B1;
    const float* biasP;
    const __half* G0h; const int* tokIdx; int tokStride;
    __half* c; __half* outh;
};

__device__ __forceinline__ void lstm_body(const LstmParams& P)
{
    GEMM_PROLOGUE
    const int nChunks = P.nPairs * 8;
#define SRCS_LSTM(cc, Ap, Bp, kt) { int pair_ = (cc) >> 3;                      \
        kt = ((cc) & 7) * 32;                                                    \
        Ap = pair_ ? P.A1 : P.A0; Bp = pair_ ? P.B1 : P.B0; }
    GEMM_MAINLOOP(nChunks, SRCS_LSTM)
#undef SRCS_LSTM

#pragma unroll
    for (int mt = 0; mt < 2; mt++) {
        int r0 = mBase + wM + mt * 16 + (lane >> 2);
        int r1 = r0 + 8;
        const __half *g0 = nullptr, *g1 = nullptr;
        if (P.G0h) {
            g0 = P.G0h + (size_t)P.tokIdx[(size_t)r0 * P.tokStride] * k4H;
            g1 = P.G0h + (size_t)P.tokIdx[(size_t)r1 * P.tokStride] * k4H;
        }
#pragma unroll
        for (int nt = 0; nt < 4; nt++) {
            int n = nBase + wN + nt * 8 + (lane & 3) * 2;
            float z0 = acc[mt][nt][0] + P.biasP[n];
            float z1 = acc[mt][nt][1] + P.biasP[n + 1];
            float z2 = acc[mt][nt][2] + P.biasP[n];
            float z3 = acc[mt][nt][3] + P.biasP[n + 1];
            if (g0) {
                __half2 a0 = *(const __half2*)(g0 + n);
                __half2 a1 = *(const __half2*)(g1 + n);
                z0 += __half2float(a0.x); z1 += __half2float(a0.y);
                z2 += __half2float(a1.x); z3 += __half2float(a1.y);
            }
            float e0 = __shfl_xor_sync(0xffffffffu, z0, 1);
            float e1 = __shfl_xor_sync(0xffffffffu, z1, 1);
            float e2 = __shfl_xor_sync(0xffffffffu, z2, 1);
            float e3 = __shfl_xor_sync(0xffffffffu, z3, 1);
            bool evn = (lane & 1) == 0;
            int row = evn ? r0 : r1;
            float zi = evn ? z0 : e2;
            float zf = evn ? z1 : e3;
            float zg = evn ? e0 : z2;
            float zo = evn ? e1 : z3;
            int uG = ((nBase + wN + nt * 8) >> 2) + ((lane & 3) >> 1);
            size_t idx = (size_t)row * kH + uG;
            float cn = sigm(zf) * __half2float(P.c[idx]) + sigm(zi) * tanhf(zg);
            P.c[idx] = __float2half(cn);
            float hn = sigm(zo) * tanhf(cn);
            P.outh[idx] = __float2half(hn);
        }
    }
}

__global__ void __launch_bounds__(256, 3) mma_lstm1(LstmParams pa)
{
    lstm_body(pa);
}
// merged wavefront: z=0 runs layer1(t), z=1 runs layer0(t+1) — independent
__global__ void __launch_bounds__(256, 3) mma_lstm2(LstmParams pa, LstmParams pb)
{
    lstm_body(blockIdx.z ? pb : pa);
}

// ---------------- t=0 layer-0 special case: h0=0 -> z = G0[token] + bias ------
__global__ void __launch_bounds__(256) lstm0_init_kernel(
    const int* __restrict__ tokIdx, int tokStride,
    const __half* __restrict__ G0h, const float* __restrict__ bP0,
    __half* __restrict__ c, __half* __restrict__ outh)
{
    int idx = blockIdx.x * 256 + threadIdx.x;     // m*kH + u
    int m = idx >> 8, u = idx & 255;
    int tok = tokIdx[(size_t)m * tokStride];
    const __half2* g = (const __half2*)(G0h + (size_t)tok * k4H + u * 4);
    __half2 ga = g[0], gb = g[1];
    const float4 bv = *(const float4*)(bP0 + u * 4);
    float zi = __half2float(ga.x) + bv.x;
    float zg = __half2float(gb.x) + bv.z;
    float zo = __half2float(gb.y) + bv.w;
    float cn = sigm(zi) * tanhf(zg);              // f-term vanishes (c=0)
    c[idx] = __float2half(cn);
    outh[idx] = __float2half(sigm(zo) * tanhf(cn));
}

// ---------------- consolidated weight prep ------------------------------------
__global__ void __launch_bounds__(256) prep_weights_kernel(
    const float* __restrict__ Wi0, const float* __restrict__ Wh0,
    const float* __restrict__ Wi1, const float* __restrict__ Wh1,
    const float* __restrict__ Wk,
    const float* __restrict__ b0, const float* __restrict__ b1,
    __half* __restrict__ Wi0T, __half* __restrict__ Wh0T,
    __half* __restrict__ Wi1T, __half* __restrict__ Wh1T,
    __half* __restrict__ WkT, float* __restrict__ bP0, float* __restrict__ bP1)
{
    int blk = blockIdx.x;
    if (blk < 512) {
        const float* W; __half* T;
        switch (blk >> 7) {
            case 0: W = Wi0; T = Wi0T; break;
            case 1: W = Wh0; T = Wh0T; break;
            case 2: W = Wi1; T = Wi1T; break;
            default: W = Wh1; T = Wh1T;
        }
        int n = (blk & 127) * 8 + (threadIdx.x >> 5);
        int lane = threadIdx.x & 31;
        int col = (n & 3) * kH + (n >> 2);
        for (int kk = lane; kk < kH; kk += 32)
            T[(size_t)n * kH + kk] = __float2half(W[(size_t)kk * k4H + col]);
    } else if (blk < 544) {
        int n = (blk - 512) * 8 + (threadIdx.x >> 5);
        int lane = threadIdx.x & 31;
        for (int kk = lane; kk < kH; kk += 32)
            WkT[(size_t)n * kH + kk] = __float2half(Wk[(size_t)kk * kH + n]);
    } else {
        int i = blk - 544;                       // 0..7
        const float* b = (i < 4) ? b0 : b1;
        float* bP = (i < 4) ? bP0 : bP1;
        int n = (i & 3) * 256 + threadIdx.x;
        bP[n] = b[(n & 3) * kH + (n >> 2)];
    }
}

__global__ void __launch_bounds__(256) convert_embed_kernel(
    const float4* __restrict__ x, __half2* __restrict__ h2, int n4)
{
    int i = blockIdx.x * 256 + threadIdx.x;
    if (i >= n4) return;
    float4 v = x[i];
    h2[i * 2 + 0] = __halves2half2(__float2half(v.x), __float2half(v.y));
    h2[i * 2 + 1] = __halves2half2(__float2half(v.z), __float2half(v.w));
}

// ---------------- CSR build (once per launch; topology static) ----------------
__global__ void csr_zero_kernel()
{
    int i = blockIdx.x * 256 + threadIdx.x;
    g_cnt[i] = 0;
    g_cur[i] = 0;
}
__global__ void csr_count_kernel(const int* __restrict__ dst)
{
    int e = blockIdx.x * 256 + threadIdx.x;
    int node = (e / kE) * kN + dst[e];
    atomicAdd(&g_cnt[node], 1);
}
__global__ void __launch_bounds__(1024) csr_scan_kernel()
{
    __shared__ int sh[1024];
    __shared__ int carry;
    int tid = threadIdx.x;
    if (tid == 0) carry = 0;
    __syncthreads();
    for (int chunk = 0; chunk < kM / 1024; chunk++) {
        int i = chunk * 1024 + tid;
        int v = g_cnt[i];
        sh[tid] = v;
        __syncthreads();
        for (int o = 1; o < 1024; o <<= 1) {
            int t = (tid >= o) ? sh[tid - o] : 0;
            __syncthreads();
            sh[tid] += t;
            __syncthreads();
        }
        g_off[i] = carry + sh[tid] - v;     // exclusive
        __syncthreads();
        if (tid == 1023) carry += sh[1023];
        __syncthreads();
    }
    if (tid == 0) g_off[kM] = carry;
}
__global__ void csr_scatter_kernel(const int* __restrict__ dst)
{
    int e = blockIdx.x * 256 + threadIdx.x;
    int node = (e / kE) * kN + dst[e];
    int pos = g_off[node] + atomicAdd(&g_cur[node], 1);
    g_eidx[pos] = e;
}

// ---------------- GAT helpers -------------------------------------------------
__global__ void compute_ae_kernel(const float* __restrict__ edge_table,
                                  const float* __restrict__ Wa)
{
    int w = threadIdx.x >> 5, lane = threadIdx.x & 31;
    if (w >= 6) return;
    float s = 0.f;
    for (int hh = lane; hh < kH; hh += 32) s += edge_table[w * kH + hh] * Wa[hh];
#pragma unroll
    for (int o = 16; o; o >>= 1) s += __shfl_down_sync(0xffffffffu, s, o);
    if (!lane) g_ae[w] = s;
}

__global__ void init_akaq_kernel()
{
    int i = blockIdx.x * 256 + threadIdx.x;
    g_ak[i] = 0.f;
    g_aq[i] = 0.f;
}

// gather with fused edge scoring: one warp per dst node; writes fp16 se only.
__global__ void __launch_bounds__(256) node_gather_kernel(
    const int* __restrict__ src, const int* __restrict__ et,
    const int* __restrict__ steps, int step, const float* __restrict__ ba,
    const float* __restrict__ edge_table,
    const __half* __restrict__ keysh, __half* __restrict__ seh)
{
    int node = blockIdx.x * 8 + (threadIdx.x >> 5);
    int lane = threadIdx.x & 31;
    int b = node / kN;
    if (step >= steps[b]) return;
    int lo = g_off[node], hi = g_off[node + 1];
    float acc[8] = {0, 0, 0, 0, 0, 0, 0, 0};
    float sum_ex = 0.f;
    int base = b * kN;
    float aq_ba = g_aq[node] + ba[0];
    for (int i = lo; i < hi; i++) {
        int e = g_eidx[i];
        int s = src[e], t = et[e];
        float lg = g_ak[base + s] + g_ae[t] + aq_ba;
        lg = fmaxf(0.2f * lg, lg);
        float ex = expf(lg);
        sum_ex += ex;
        const __half2* kr = (const __half2*)(keysh + (size_t)(base + s) * kH + lane * 8);
        const float4* er = (const float4*)(edge_table + t * kH + lane * 8);
        __half2 k0 = kr[0], k1 = kr[1], k2 = kr[2], k3 = kr[3];
        float4 e0 = er[0], e1 = er[1];
        acc[0] += (__half2float(k0.x) + e0.x) * ex;
        acc[1] += (__half2float(k0.y) + e0.y) * ex;
        acc[2] += (__half2float(k1.x) + e0.z) * ex;
        acc[3] += (__half2float(k1.y) + e0.w) * ex;
        acc[4] += (__half2float(k2.x) + e1.x) * ex;
        acc[5] += (__half2float(k2.y) + e1.y) * ex;
        acc[6] += (__half2float(k3.x) + e1.z) * ex;
        acc[7] += (__half2float(k3.y) + e1.w) * ex;
    }
    float inv = (hi > lo) ? (1.f / sum_ex) : 0.f;
    __half2* hrow = (__half2*)(seh + (size_t)node * kH + lane * 8);
    hrow[0] = __halves2half2(__float2half(acc[0] * inv), __float2half(acc[1] * inv));
    hrow[1] = __halves2half2(__float2half(acc[2] * inv), __float2half(acc[3] * inv));
    hrow[2] = __halves2half2(__float2half(acc[4] * inv), __float2half(acc[5] * inv));
    hrow[3] = __halves2half2(__float2half(acc[6] * inv), __float2half(acc[7] * inv));
}

// ---------------- final gather + dense (reads fp16 se) ------------------------
__global__ void __launch_bounds__(256) final_kernel(
    const __half* __restrict__ seh, const int* __restrict__ exit_index,
    const float* __restrict__ Wo, const float* __restrict__ bo,
    float* __restrict__ out)
{
    __shared__ float fin[kH];
    int b = blockIdx.x, tid = threadIdx.x;
    const __half* row = seh + ((size_t)b * kN + exit_index[b]) * kH;
    if (tid < kH) fin[tid] = __half2float(row[tid]);
    __syncthreads();
    for (int j = tid; j < kOV; j += 256) {
        float s = bo[j];
        for (int hh = 0; hh < kH; hh++) s += fin[hh] * Wo[(size_t)hh * kOV + j];
        out[b * kOV + j] = s;
    }
}

// ---------------- driver ------------------------------------------------------
extern "C" void kernel_launch(void* const* d_in, const int* in_sizes, int n_in,
                              void* d_out, int out_size)
{
    const int*   data       = (const int*)d_in[0];
    const int*   src        = (const int*)d_in[1];
    const int*   dst        = (const int*)d_in[2];
    const int*   et         = (const int*)d_in[3];
    const int*   steps      = (const int*)d_in[4];
    const int*   exit_index = (const int*)d_in[5];
    const float* embed      = (const float*)d_in[6];
    const float* Wi0        = (const float*)d_in[7];
    const float* Wh0        = (const float*)d_in[8];
    const float* b0         = (const float*)d_in[9];
    const float* Wi1        = (const float*)d_in[10];
    const float* Wh1        = (const float*)d_in[11];
    const float* b1         = (const float*)d_in[12];
    const float* Wk         = (const float*)d_in[13];
    const float* bk         = (const float*)d_in[14];
    const float* Wa         = (const float*)d_in[15];
    const float* ba         = (const float*)d_in[16];
    const float* edge_table = (const float*)d_in[17];
    const float* Wo         = (const float*)d_in[18];
    const float* bo         = (const float*)d_in[19];
    float* out = (float*)d_out;

    float *bP0, *bP1;
    __half *G0h, *c0, *c1, *h0h, *h1h, *embh, *keysh;
    __half *Wi0T, *Wh0T, *Wi1T, *Wh1T, *WkT;
    cudaGetSymbolAddress((void**)&G0h,   g_G0h);
    cudaGetSymbolAddress((void**)&c0,    g_c0);
    cudaGetSymbolAddress((void**)&c1,    g_c1);
    cudaGetSymbolAddress((void**)&keysh, g_keysh);
    cudaGetSymbolAddress((void**)&h0h,   g_h0h);
    cudaGetSymbolAddress((void**)&h1h,   g_h1h);
    cudaGetSymbolAddress((void**)&embh,  g_embh);
    cudaGetSymbolAddress((void**)&Wi0T,  g_Wi0T);
    cudaGetSymbolAddress((void**)&Wh0T,  g_Wh0T);
    cudaGetSymbolAddress((void**)&Wi1T,  g_Wi1T);
    cudaGetSymbolAddress((void**)&Wh1T,  g_Wh1T);
    cudaGetSymbolAddress((void**)&WkT,   g_WkT);
    cudaGetSymbolAddress((void**)&bP0,   g_bP0);
    cudaGetSymbolAddress((void**)&bP1,   g_bP1);

    cudaFuncSetAttribute(mma_gemm, cudaFuncAttributeMaxDynamicSharedMemorySize, GEMM_SMEM);
    cudaFuncSetAttribute(mma_lstm1, cudaFuncAttributeMaxDynamicSharedMemorySize, GEMM_SMEM);
    cudaFuncSetAttribute(mma_lstm2, cudaFuncAttributeMaxDynamicSharedMemorySize, GEMM_SMEM);

    const size_t hElems = (size_t)kM * kH;
    cudaMemsetAsync(c1, 0, hElems * 2);   // L1(0) epilogue reads c1

    prep_weights_kernel<<<552, 256>>>(Wi0, Wh0, Wi1, Wh1, Wk, b0, b1,
                                      Wi0T, Wh0T, Wi1T, Wh1T, WkT, bP0, bP1);
    convert_embed_kernel<<<(kV * kH / 4 + 255) / 256, 256>>>(
        (const float4*)embed, (__half2*)embh, kV * kH / 4);

    // CSR build (static topology: once per launch)
    csr_zero_kernel<<<kM / 256, 256>>>();
    csr_count_kernel<<<kET / 256, 256>>>(dst);
    csr_scan_kernel<<<1, 1024>>>();
    csr_scatter_kernel<<<kET / 256, 256>>>(dst);

    // G0 = embed @ Wi0 (gate-permuted, fp16)  [32000, 1024]
    mma_gemm<<<dim3(k4H / 64, kV / 128), 256, GEMM_SMEM>>>(
        kV, k4H, embh, Wi0T, nullptr, nullptr, G0h, nullptr, 0, nullptr);

    // ---- LSTM wavefront ----
    auto L0 = [&](int t) {
        LstmParams p{};
        p.nPairs = 1;
        p.A0 = h0h + (size_t)(t & 1) * hElems;  p.B0 = Wh0T;
        p.biasP = bP0;
        p.G0h = G0h; p.tokIdx = data + t; p.tokStride = kL;
        p.c = c0;
        p.outh = h0h + (size_t)((t & 1) ^ 1) * hElems;
        return p;
    };
    auto L1 = [&](int t) {
        LstmParams p{};
        p.nPairs = 2;
        p.A0 = h0h + (size_t)((t & 1) ^ 1) * hElems;  p.B0 = Wi1T;  // h0(t)
        p.A1 = h1h + (size_t)(t & 1) * hElems;        p.B1 = Wh1T;
        p.biasP = bP1;
        p.c = c1;
        p.outh = h1h + (size_t)((t & 1) ^ 1) * hElems;
        return p;
    };
    // t=0, layer 0: GEMM is zero (h0=0) -> pure gather+gates; writes buffer 1
    lstm0_init_kernel<<<kM * kH / 256, 256>>>(data, kL, G0h, bP0,
                                              c0, h0h + hElems);
    {   // t=0, layer 1: h1=0 -> drop the Wh1 pair; merged with L0(1)
        LstmParams l10 = L1(0);
        l10.nPairs = 1;
        mma_lstm2<<<dim3(k4H / 64, kM / 128, 2), 256, GEMM_SMEM>>>(l10, L0(1));
    }
    for (int t = 1; t < kL - 1; t++)
        mma_lstm2<<<dim3(k4H / 64, kM / 128, 2), 256, GEMM_SMEM>>>(L1(t), L0(t + 1));
    mma_lstm1<<<dim3(k4H / 64, kM / 128), 256, GEMM_SMEM>>>(L1(kL - 1));
    // final h1 fp16 in buffer 0 (t=7 writes wb=0) == live se state

    compute_ae_kernel<<<1, 256>>>(edge_table, Wa);

    for (int step = 0; step < kMaxSteps; step++) {
        init_akaq_kernel<<<kM / 256, 256>>>();
        // keys (fp16) = se @ Wk + bk, with fused partial ak/aq dots
        mma_gemm<<<dim3(kH / 64, kM / 128), 256, GEMM_SMEM>>>(
            kM, kH, h1h, WkT, bk, nullptr, keysh, steps, step, Wa);
        node_gather_kernel<<<kM / 8, 256>>>(src, et, steps, step, ba,
                                            edge_table, keysh, h1h);
        // h1h (buffer 0) holds updated se fp16 for next keys GEMM / final
    }

    final_kernel<<<kB, 256>>>(h1h, exit_index, Wo, bo, out);
}

// round 16
// speedup vs baseline: 1.0463x; 1.0022x over previous
#include <cuda_runtime.h>
#include <cuda_fp16.h>
#include <math.h>
#include <stdint.h>

namespace {
constexpr int kB = 8, kN = 4096, kL = 8, kE = 16384, kH = 256;
constexpr int kV = 32000, kOV = 512, kMaxSteps = 6;
constexpr int kM = kB * kN;        // 32768
constexpr int k4H = 4 * kH;        // 1024
constexpr int kET = kB * kE;       // 131072 total edges
constexpr int STAGES = 4;
constexpr int TILE_A = 128 * 80;   // 10240
constexpr int TILE_BB = 64 * 80;   // 5120
constexpr int STAGE_B = TILE_A + TILE_BB;              // 15360
constexpr int GEMM_SMEM = STAGES * STAGE_B;            // 61440 -> 3 CTAs/SM
}

// ---------------- scratch ---------------------------------------------------
__device__ __half g_G0h[(size_t)kV * k4H];        // embed @ Wi0, fp16, gate-permuted
__device__ __half g_c0[kM * kH], g_c1[kM * kH];
__device__ __half g_h0h[2][kM * kH];
__device__ __half g_h1h[2][kM * kH];              // buffer 0 doubles as se fp16
__device__ float g_se[kM * kH];
__device__ __half g_embh[(size_t)kV * kH];
__device__ __half g_Wi0T[k4H * kH], g_Wh0T[k4H * kH];
__device__ __half g_Wi1T[k4H * kH], g_Wh1T[k4H * kH];
__device__ __half g_WkT[kH * kH];
__device__ float g_bP0[k4H], g_bP1[k4H];
__device__ __half g_keysh[kM * kH];
__device__ float g_akq[4][kM];                    // ping-pong: ak0,aq0,ak1,aq1
__device__ float g_ae[8];
// CSR by destination node (built once per launch; topology is static)
__device__ int g_cnt[kM], g_cur[kM], g_off[kM + 1], g_eidx[kET];

// ---------------- PTX helpers ----------------------------------------------
__device__ __forceinline__ uint32_t smem_u32(const void* p) {
    uint32_t a;
    asm("{ .reg .u64 t; cvta.to.shared.u64 t, %1; cvt.u32.u64 %0, t; }"
        : "=r"(a) : "l"(p));
    return a;
}
__device__ __forceinline__ void cpasync16(uint32_t dst, const void* src) {
    asm volatile("cp.async.cg.shared.global [%0], [%1], 16;"
                 :: "r"(dst), "l"(src) : "memory");
}
__device__ __forceinline__ void cp_commit() {
    asm volatile("cp.async.commit_group;" ::: "memory");
}
template <int N>
__device__ __forceinline__ void cp_wait() {
    asm volatile("cp.async.wait_group %0;" :: "n"(N) : "memory");
}
__device__ __forceinline__ void ldsm4(uint32_t* r, uint32_t a) {
    asm volatile("ldmatrix.sync.aligned.m8n8.x4.shared.b16 {%0,%1,%2,%3}, [%4];"
                 : "=r"(r[0]), "=r"(r[1]), "=r"(r[2]), "=r"(r[3]) : "r"(a));
}
__device__ __forceinline__ void mma16816(float* d, const uint32_t* a, const uint32_t* b) {
    asm volatile(
        "mma.sync.aligned.m16n8k16.row.col.f32.f16.f16.f32 "
        "{%0,%1,%2,%3}, {%4,%5,%6,%7}, {%8,%9}, {%0,%1,%2,%3};"
        : "+f"(d[0]), "+f"(d[1]), "+f"(d[2]), "+f"(d[3])
        : "r"(a[0]), "r"(a[1]), "r"(a[2]), "r"(a[3]), "r"(b[0]), "r"(b[1]));
}
__device__ __forceinline__ float sigm(float x) { return 1.f / (1.f + expf(-x)); }

// ---------------- shared GEMM mainloop pieces --------------------------------
// CTA tile 128(M) x 64(N), K-chunk 32, 4 stages (round-13 proven config).
#define GEMM_PROLOGUE                                                            \
    extern __shared__ __align__(128) char smem[];                               \
    const int tid = threadIdx.x, wid = tid >> 5, lane = tid & 31;               \
    const int mBase = blockIdx.y * 128, nBase = blockIdx.x * 64;                \
    const int wM = (wid & 3) * 32, wN = (wid >> 2) * 32;                        \
    const uint32_t sbase = smem_u32(smem);                                      \
    float acc[2][4][4];                                                         \
    _Pragma("unroll") for (int i = 0; i < 2; i++)                               \
    _Pragma("unroll") for (int j = 0; j < 4; j++)                               \
    _Pragma("unroll") for (int k = 0; k < 4; k++) acc[i][j][k] = 0.f;

__device__ __forceinline__ void load_tiles(uint32_t sbase, int buf, int tid,
        const __half* __restrict__ Ap, const __half* __restrict__ Bp,
        int mBase, int nBase, int kt) {
    const uint32_t sA = sbase + (uint32_t)buf * STAGE_B;
    const uint32_t sB = sA + TILE_A;
#pragma unroll
    for (int i = 0; i < 2; i++) {
        int idx = i * 256 + tid;
        int r = idx >> 2, c4 = idx & 3;
        cpasync16(sA + r * 80 + c4 * 16,
                  Ap + (size_t)(mBase + r) * 256 + kt + c4 * 8);
    }
    {
        int r = tid >> 2, c4 = tid & 3;
        cpasync16(sB + r * 80 + c4 * 16,
                  Bp + (size_t)(nBase + r) * 256 + kt + c4 * 8);
    }
    cp_commit();
}

__device__ __forceinline__ void compute_tiles(uint32_t sbase, int buf,
        int wM, int wN, int lane, float acc[2][4][4]) {
    const uint32_t sA = sbase + (uint32_t)buf * STAGE_B;
    const uint32_t sB = sA + TILE_A;
#pragma unroll
    for (int ks = 0; ks < 2; ks++) {
        uint32_t a[2][4];
#pragma unroll
        for (int mt = 0; mt < 2; mt++) {
            int row = wM + mt * 16 + (lane & 15);
            ldsm4(a[mt], sA + row * 80 + ((lane >> 4) * 16) + ks * 32);
        }
#pragma unroll
        for (int nt2 = 0; nt2 < 2; nt2++) {
            uint32_t b[4];
            int nrow = wN + nt2 * 16 + (lane & 7) + ((lane >> 4) << 3);
            ldsm4(b, sB + nrow * 80 + (((lane >> 3) & 1) * 16) + ks * 32);
            mma16816(acc[0][nt2 * 2 + 0], a[0], b + 0);
            mma16816(acc[0][nt2 * 2 + 1], a[0], b + 2);
            mma16816(acc[1][nt2 * 2 + 0], a[1], b + 0);
            mma16816(acc[1][nt2 * 2 + 1], a[1], b + 2);
        }
    }
}

#define GEMM_MAINLOOP(NCHUNKS, SRCS)                                            \
    {                                                                            \
        const __half *Ap_, *Bp_; int kt_;                                        \
        _Pragma("unroll") for (int s = 0; s < STAGES - 1; s++) {                 \
            if (s < (NCHUNKS)) { SRCS(s, Ap_, Bp_, kt_);                         \
                load_tiles(sbase, s, tid, Ap_, Bp_, mBase, nBase, kt_); }        \
            else cp_commit();                                                    \
        }                                                                        \
        for (int c = 0; c < (NCHUNKS); ++c) {                                   \
            cp_wait<STAGES - 2>();                                               \
            __syncthreads();                                                     \
            int pre = c + STAGES - 1;                                            \
            if (pre < (NCHUNKS)) { SRCS(pre, Ap_, Bp_, kt_);                     \
                load_tiles(sbase, pre & (STAGES - 1), tid, Ap_, Bp_,             \
                           mBase, nBase, kt_); }                                 \
            else cp_commit();                                                    \
            compute_tiles(sbase, c & (STAGES - 1), wM, wN, lane, acc);           \
        }                                                                        \
    }

// ---------------- generic 1-pass fp16 GEMM (G0 precompute, keys) -------------
__global__ void __launch_bounds__(256, 3) mma_gemm(
    int M, int NTotal,
    const __half* __restrict__ A, const __half* __restrict__ B,
    const float* __restrict__ bias, float* __restrict__ C,
    __half* __restrict__ Ch,
    const int* __restrict__ steps, int step, const float* __restrict__ Wa,
    float* __restrict__ akOut, float* __restrict__ aqOut)
{
    if (steps && step >= steps[(blockIdx.y * 128) / kN]) return;
    GEMM_PROLOGUE
#define SRCS_PLAIN(c, Ap, Bp, kt) { Ap = A; Bp = B; kt = (c) * 32; }
    GEMM_MAINLOOP(8, SRCS_PLAIN)
#undef SRCS_PLAIN

#pragma unroll
    for (int mt = 0; mt < 2; mt++) {
        int r0 = mBase + wM + mt * 16 + (lane >> 2);
        int r1 = r0 + 8;
        float ak0 = 0.f, aq0 = 0.f, ak1 = 0.f, aq1 = 0.f;
#pragma unroll
        for (int nt = 0; nt < 4; nt++) {
            int n = nBase + wN + nt * 8 + (lane & 3) * 2;
            float2 v0 = make_float2(acc[mt][nt][0], acc[mt][nt][1]);
            float2 v1 = make_float2(acc[mt][nt][2], acc[mt][nt][3]);
            if (bias) {
                float2 bv = *(const float2*)(bias + n);
                v0.x += bv.x; v0.y += bv.y; v1.x += bv.x; v1.y += bv.y;
            }
            if (Ch) {
                *(__half2*)(Ch + (size_t)r0 * NTotal + n) =
                    __halves2half2(__float2half(v0.x), __float2half(v0.y));
                *(__half2*)(Ch + (size_t)r1 * NTotal + n) =
                    __halves2half2(__float2half(v1.x), __float2half(v1.y));
            }
            if (C) {
                *(float2*)(C + (size_t)r0 * NTotal + n) = v0;
                *(float2*)(C + (size_t)r1 * NTotal + n) = v1;
            }
            if (Wa) {
                float2 w1 = *(const float2*)(Wa + n);
                float2 w2 = *(const float2*)(Wa + kH + n);
                ak0 += v0.x * w1.x + v0.y * w1.y;
                aq0 += v0.x * w2.x + v0.y * w2.y;
                ak1 += v1.x * w1.x + v1.y * w1.y;
                aq1 += v1.x * w2.x + v1.y * w2.y;
            }
        }
        if (Wa) {
#pragma unroll
            for (int o = 1; o <= 2; o <<= 1) {
                ak0 += __shfl_xor_sync(0xffffffffu, ak0, o);
                aq0 += __shfl_xor_sync(0xffffffffu, aq0, o);
                ak1 += __shfl_xor_sync(0xffffffffu, ak1, o);
                aq1 += __shfl_xor_sync(0xffffffffu, aq1, o);
            }
            if ((lane & 3) == 0) {
                atomicAdd(&akOut[r0], ak0);
                atomicAdd(&aqOut[r0], aq0);
                atomicAdd(&akOut[r1], ak1);
                atomicAdd(&aqOut[r1], aq1);
            }
        }
    }
}

// ---------------- fused LSTM GEMM + gates (1-pass fp16) -----------------------
struct LstmParams {
    int nPairs;
    const __half* A0; const __half* B0;
    const __half* A1; const __half* B1;
    const float* biasP;
    const __half* G0h; const int* tokIdx; int tokStride;
    __half* c; __half* outh; float* seOut;
};

__device__ __forceinline__ void lstm_body(const LstmParams& P)
{
    GEMM_PROLOGUE
    const int nChunks = P.nPairs * 8;
#define SRCS_LSTM(cc, Ap, Bp, kt) { int pair_ = (cc) >> 3;                      \
        kt = ((cc) & 7) * 32;                                                    \
        Ap = pair_ ? P.A1 : P.A0; Bp = pair_ ? P.B1 : P.B0; }
    GEMM_MAINLOOP(nChunks, SRCS_LSTM)
#undef SRCS_LSTM

#pragma unroll
    for (int mt = 0; mt < 2; mt++) {
        int r0 = mBase + wM + mt * 16 + (lane >> 2);
        int r1 = r0 + 8;
        const __half *g0 = nullptr, *g1 = nullptr;
        if (P.G0h) {
            g0 = P.G0h + (size_t)P.tokIdx[(size_t)r0 * P.tokStride] * k4H;
            g1 = P.G0h + (size_t)P.tokIdx[(size_t)r1 * P.tokStride] * k4H;
        }
#pragma unroll
        for (int nt = 0; nt < 4; nt++) {
            int n = nBase + wN + nt * 8 + (lane & 3) * 2;
            float z0 = acc[mt][nt][0] + P.biasP[n];
            float z1 = acc[mt][nt][1] + P.biasP[n + 1];
            float z2 = acc[mt][nt][2] + P.biasP[n];
            float z3 = acc[mt][nt][3] + P.biasP[n + 1];
            if (g0) {
                __half2 a0 = *(const __half2*)(g0 + n);
                __half2 a1 = *(const __half2*)(g1 + n);
                z0 += __half2float(a0.x); z1 += __half2float(a0.y);
                z2 += __half2float(a1.x); z3 += __half2float(a1.y);
            }
            float e0 = __shfl_xor_sync(0xffffffffu, z0, 1);
            float e1 = __shfl_xor_sync(0xffffffffu, z1, 1);
            float e2 = __shfl_xor_sync(0xffffffffu, z2, 1);
            float e3 = __shfl_xor_sync(0xffffffffu, z3, 1);
            bool evn = (lane & 1) == 0;
            int row = evn ? r0 : r1;
            float zi = evn ? z0 : e2;
            float zf = evn ? z1 : e3;
            float zg = evn ? e0 : z2;
            float zo = evn ? e1 : z3;
            int uG = ((nBase + wN + nt * 8) >> 2) + ((lane & 3) >> 1);
            size_t idx = (size_t)row * kH + uG;
            float cn = sigm(zf) * __half2float(P.c[idx]) + sigm(zi) * tanhf(zg);
            P.c[idx] = __float2half(cn);
            float hn = sigm(zo) * tanhf(cn);
            P.outh[idx] = __float2half(hn);
            if (P.seOut) P.seOut[idx] = hn;
        }
    }
}

__global__ void __launch_bounds__(256, 3) mma_lstm1(LstmParams pa)
{
    lstm_body(pa);
}
// merged wavefront: z=0 runs layer1(t), z=1 runs layer0(t+1) — independent
__global__ void __launch_bounds__(256, 3) mma_lstm2(LstmParams pa, LstmParams pb)
{
    lstm_body(blockIdx.z ? pb : pa);
}

// ---------------- t=0 layer-0 special case: h0=0 -> z = G0[token] + bias ------
__global__ void __launch_bounds__(256) lstm0_init_kernel(
    const int* __restrict__ tokIdx, int tokStride,
    const __half* __restrict__ G0h, const float* __restrict__ bP0,
    __half* __restrict__ c, __half* __restrict__ outh)
{
    int idx = blockIdx.x * 256 + threadIdx.x;     // m*kH + u
    int m = idx >> 8, u = idx & 255;
    int tok = tokIdx[(size_t)m * tokStride];
    const __half2* g = (const __half2*)(G0h + (size_t)tok * k4H + u * 4);
    __half2 ga = g[0], gb = g[1];
    const float4 bv = *(const float4*)(bP0 + u * 4);
    float zi = __half2float(ga.x) + bv.x;
    float zg = __half2float(gb.x) + bv.z;
    float zo = __half2float(gb.y) + bv.w;
    float cn = sigm(zi) * tanhf(zg);              // f-term vanishes (c=0)
    c[idx] = __float2half(cn);
    outh[idx] = __float2half(sigm(zo) * tanhf(cn));
}

// ---------------- consolidated weight prep (incl. ae dots, block 552) ---------
__global__ void __launch_bounds__(256) prep_weights_kernel(
    const float* __restrict__ Wi0, const float* __restrict__ Wh0,
    const float* __restrict__ Wi1, const float* __restrict__ Wh1,
    const float* __restrict__ Wk,
    const float* __restrict__ b0, const float* __restrict__ b1,
    const float* __restrict__ edge_table, const float* __restrict__ Wa,
    __half* __restrict__ Wi0T, __half* __restrict__ Wh0T,
    __half* __restrict__ Wi1T, __half* __restrict__ Wh1T,
    __half* __restrict__ WkT, float* __restrict__ bP0, float* __restrict__ bP1)
{
    int blk = blockIdx.x;
    if (blk < 512) {
        const float* W; __half* T;
        switch (blk >> 7) {
            case 0: W = Wi0; T = Wi0T; break;
            case 1: W = Wh0; T = Wh0T; break;
            case 2: W = Wi1; T = Wi1T; break;
            default: W = Wh1; T = Wh1T;
        }
        int n = (blk & 127) * 8 + (threadIdx.x >> 5);
        int lane = threadIdx.x & 31;
        int col = (n & 3) * kH + (n >> 2);
        for (int kk = lane; kk < kH; kk += 32)
            T[(size_t)n * kH + kk] = __float2half(W[(size_t)kk * k4H + col]);
    } else if (blk < 544) {
        int n = (blk - 512) * 8 + (threadIdx.x >> 5);
        int lane = threadIdx.x & 31;
        for (int kk = lane; kk < kH; kk += 32)
            WkT[(size_t)n * kH + kk] = __float2half(Wk[(size_t)kk * kH + n]);
    } else if (blk < 552) {
        int i = blk - 544;                       // 0..7
        const float* b = (i < 4) ? b0 : b1;
        float* bP = (i < 4) ? bP0 : bP1;
        int n = (i & 3) * 256 + threadIdx.x;
        bP[n] = b[(n & 3) * kH + (n >> 2)];
    } else {
        // ae[w] = edge_table[w] . Wa[:256]
        int w = threadIdx.x >> 5, lane = threadIdx.x & 31;
        if (w >= 6) return;
        float s = 0.f;
        for (int hh = lane; hh < kH; hh += 32)
            s += edge_table[w * kH + hh] * Wa[hh];
#pragma unroll
        for (int o = 16; o; o >>= 1) s += __shfl_down_sync(0xffffffffu, s, o);
        if (!lane) g_ae[w] = s;
    }
}

__global__ void __launch_bounds__(256) convert_embed_kernel(
    const float4* __restrict__ x, __half2* __restrict__ h2, int n4)
{
    int i = blockIdx.x * 256 + threadIdx.x;
    if (i >= n4) return;
    float4 v = x[i];
    h2[i * 2 + 0] = __halves2half2(__float2half(v.x), __float2half(v.y));
    h2[i * 2 + 1] = __halves2half2(__float2half(v.z), __float2half(v.w));
}

// ---------------- CSR build (once per launch; topology static) ----------------
__global__ void csr_zero_kernel()
{
    int i = blockIdx.x * 256 + threadIdx.x;
    g_cnt[i] = 0;
    g_cur[i] = 0;
}
__global__ void csr_count_kernel(const int* __restrict__ dst)
{
    int e = blockIdx.x * 256 + threadIdx.x;
    int node = (e / kE) * kN + dst[e];
    atomicAdd(&g_cnt[node], 1);
}
__global__ void __launch_bounds__(1024) csr_scan_kernel()
{
    __shared__ int sh[1024];
    __shared__ int carry;
    int tid = threadIdx.x;
    if (tid == 0) carry = 0;
    __syncthreads();
    for (int chunk = 0; chunk < kM / 1024; chunk++) {
        int i = chunk * 1024 + tid;
        int v = g_cnt[i];
        sh[tid] = v;
        __syncthreads();
        for (int o = 1; o < 1024; o <<= 1) {
            int t = (tid >= o) ? sh[tid - o] : 0;
            __syncthreads();
            sh[tid] += t;
            __syncthreads();
        }
        g_off[i] = carry + sh[tid] - v;     // exclusive
        __syncthreads();
        if (tid == 1023) carry += sh[1023];
        __syncthreads();
    }
    if (tid == 0) g_off[kM] = carry;
}
__global__ void csr_scatter_kernel(const int* __restrict__ dst)
{
    int e = blockIdx.x * 256 + threadIdx.x;
    int node = (e / kE) * kN + dst[e];
    int pos = g_off[node] + atomicAdd(&g_cur[node], 1);
    g_eidx[pos] = e;
}

// gather with fused edge scoring; zeroes NEXT step's ak/aq buffers (ping-pong)
__global__ void __launch_bounds__(256) node_gather_kernel(
    const int* __restrict__ src, const int* __restrict__ et,
    const int* __restrict__ steps, int step, const float* __restrict__ ba,
    const float* __restrict__ edge_table,
    const __half* __restrict__ keysh,
    const float* __restrict__ akCur, const float* __restrict__ aqCur,
    float* __restrict__ akNext, float* __restrict__ aqNext,
    float* __restrict__ se, __half* __restrict__ seh)
{
    int node = blockIdx.x * 8 + (threadIdx.x >> 5);
    int lane = threadIdx.x & 31;
    int b = node / kN;
    if (step >= steps[b]) return;
    int lo = g_off[node], hi = g_off[node + 1];
    float acc[8] = {0, 0, 0, 0, 0, 0, 0, 0};
    float sum_ex = 0.f;
    int base = b * kN;
    float aq_ba = aqCur[node] + ba[0];
    for (int i = lo; i < hi; i++) {
        int e = g_eidx[i];
        int s = src[e], t = et[e];
        float lg = akCur[base + s] + g_ae[t] + aq_ba;
        lg = fmaxf(0.2f * lg, lg);
        float ex = expf(lg);
        sum_ex += ex;
        const __half2* kr = (const __half2*)(keysh + (size_t)(base + s) * kH + lane * 8);
        const float4* er = (const float4*)(edge_table + t * kH + lane * 8);
        __half2 k0 = kr[0], k1 = kr[1], k2 = kr[2], k3 = kr[3];
        float4 e0 = er[0], e1 = er[1];
        acc[0] += (__half2float(k0.x) + e0.x) * ex;
        acc[1] += (__half2float(k0.y) + e0.y) * ex;
        acc[2] += (__half2float(k1.x) + e0.z) * ex;
        acc[3] += (__half2float(k1.y) + e0.w) * ex;
        acc[4] += (__half2float(k2.x) + e1.x) * ex;
        acc[5] += (__half2float(k2.y) + e1.y) * ex;
        acc[6] += (__half2float(k3.x) + e1.z) * ex;
        acc[7] += (__half2float(k3.y) + e1.w) * ex;
    }
    float inv = (hi > lo) ? (1.f / sum_ex) : 0.f;
    float4 o0, o1;
    o0.x = acc[0] * inv; o0.y = acc[1] * inv; o0.z = acc[2] * inv; o0.w = acc[3] * inv;
    o1.x = acc[4] * inv; o1.y = acc[5] * inv; o1.z = acc[6] * inv; o1.w = acc[7] * inv;
    float4* srow = (float4*)(se + (size_t)node * kH + lane * 8);
    srow[0] = o0;
    srow[1] = o1;
    __half2* hrow = (__half2*)(seh + (size_t)node * kH + lane * 8);
    hrow[0] = __halves2half2(__float2half(o0.x), __float2half(o0.y));
    hrow[1] = __halves2half2(__float2half(o0.z), __float2half(o0.w));
    hrow[2] = __halves2half2(__float2half(o1.x), __float2half(o1.y));
    hrow[3] = __halves2half2(__float2half(o1.z), __float2half(o1.w));
    if (lane == 0) { akNext[node] = 0.f; aqNext[node] = 0.f; }
}

// ---------------- final gather + dense ---------------------------------------
__global__ void __launch_bounds__(256) final_kernel(
    const float* __restrict__ se, const int* __restrict__ exit_index,
    const float* __restrict__ Wo, const float* __restrict__ bo,
    float* __restrict__ out)
{
    __shared__ float fin[kH];
    int b = blockIdx.x, tid = threadIdx.x;
    const float* row = se + ((size_t)b * kN + exit_index[b]) * kH;
    if (tid < kH) fin[tid] = row[tid];
    __syncthreads();
    for (int j = tid; j < kOV; j += 256) {
        float s = bo[j];
        for (int hh = 0; hh < kH; hh++) s += fin[hh] * Wo[(size_t)hh * kOV + j];
        out[b * kOV + j] = s;
    }
}

// ---------------- driver ------------------------------------------------------
extern "C" void kernel_launch(void* const* d_in, const int* in_sizes, int n_in,
                              void* d_out, int out_size)
{
    const int*   data       = (const int*)d_in[0];
    const int*   src        = (const int*)d_in[1];
    const int*   dst        = (const int*)d_in[2];
    const int*   et         = (const int*)d_in[3];
    const int*   steps      = (const int*)d_in[4];
    const int*   exit_index = (const int*)d_in[5];
    const float* embed      = (const float*)d_in[6];
    const float* Wi0        = (const float*)d_in[7];
    const float* Wh0        = (const float*)d_in[8];
    const float* b0         = (const float*)d_in[9];
    const float* Wi1        = (const float*)d_in[10];
    const float* Wh1        = (const float*)d_in[11];
    const float* b1         = (const float*)d_in[12];
    const float* Wk         = (const float*)d_in[13];
    const float* bk         = (const float*)d_in[14];
    const float* Wa         = (const float*)d_in[15];
    const float* ba         = (const float*)d_in[16];
    const float* edge_table = (const float*)d_in[17];
    const float* Wo         = (const float*)d_in[18];
    const float* bo         = (const float*)d_in[19];
    float* out = (float*)d_out;

    float *se, *bP0, *bP1, *akq;
    __half *G0h, *c0, *c1, *h0h, *h1h, *embh, *keysh;
    __half *Wi0T, *Wh0T, *Wi1T, *Wh1T, *WkT;
    cudaGetSymbolAddress((void**)&G0h,   g_G0h);
    cudaGetSymbolAddress((void**)&c0,    g_c0);
    cudaGetSymbolAddress((void**)&c1,    g_c1);
    cudaGetSymbolAddress((void**)&se,    g_se);
    cudaGetSymbolAddress((void**)&keysh, g_keysh);
    cudaGetSymbolAddress((void**)&h0h,   g_h0h);
    cudaGetSymbolAddress((void**)&h1h,   g_h1h);
    cudaGetSymbolAddress((void**)&embh,  g_embh);
    cudaGetSymbolAddress((void**)&Wi0T,  g_Wi0T);
    cudaGetSymbolAddress((void**)&Wh0T,  g_Wh0T);
    cudaGetSymbolAddress((void**)&Wi1T,  g_Wi1T);
    cudaGetSymbolAddress((void**)&Wh1T,  g_Wh1T);
    cudaGetSymbolAddress((void**)&WkT,   g_WkT);
    cudaGetSymbolAddress((void**)&bP0,   g_bP0);
    cudaGetSymbolAddress((void**)&bP1,   g_bP1);
    cudaGetSymbolAddress((void**)&akq,   g_akq);
    float* ak[2] = { akq,            akq + 2 * kM };
    float* aq[2] = { akq + kM,       akq + 3 * kM };

    cudaFuncSetAttribute(mma_gemm, cudaFuncAttributeMaxDynamicSharedMemorySize, GEMM_SMEM);
    cudaFuncSetAttribute(mma_lstm1, cudaFuncAttributeMaxDynamicSharedMemorySize, GEMM_SMEM);
    cudaFuncSetAttribute(mma_lstm2, cudaFuncAttributeMaxDynamicSharedMemorySize, GEMM_SMEM);

    const size_t hElems = (size_t)kM * kH;
    cudaMemsetAsync(c1, 0, hElems * 2);   // L1(0) epilogue reads c1
    cudaMemsetAsync(akq, 0, 4 * kM * sizeof(float));  // both ak/aq buffers

    prep_weights_kernel<<<553, 256>>>(Wi0, Wh0, Wi1, Wh1, Wk, b0, b1,
                                      edge_table, Wa,
                                      Wi0T, Wh0T, Wi1T, Wh1T, WkT, bP0, bP1);
    convert_embed_kernel<<<(kV * kH / 4 + 255) / 256, 256>>>(
        (const float4*)embed, (__half2*)embh, kV * kH / 4);

    // CSR build (static topology: once per launch)
    csr_zero_kernel<<<kM / 256, 256>>>();
    csr_count_kernel<<<kET / 256, 256>>>(dst);
    csr_scan_kernel<<<1, 1024>>>();
    csr_scatter_kernel<<<kET / 256, 256>>>(dst);

    // G0 = embed @ Wi0 (gate-permuted, fp16)  [32000, 1024]
    mma_gemm<<<dim3(k4H / 64, kV / 128), 256, GEMM_SMEM>>>(
        kV, k4H, embh, Wi0T, nullptr, nullptr, G0h, nullptr, 0,
        nullptr, nullptr, nullptr);

    // ---- LSTM wavefront ----
    auto L0 = [&](int t) {
        LstmParams p{};
        p.nPairs = 1;
        p.A0 = h0h + (size_t)(t & 1) * hElems;  p.B0 = Wh0T;
        p.biasP = bP0;
        p.G0h = G0h; p.tokIdx = data + t; p.tokStride = kL;
        p.c = c0;
        p.outh = h0h + (size_t)((t & 1) ^ 1) * hElems;
        p.seOut = nullptr;
        return p;
    };
    auto L1 = [&](int t) {
        LstmParams p{};
        p.nPairs = 2;
        p.A0 = h0h + (size_t)((t & 1) ^ 1) * hElems;  p.B0 = Wi1T;  // h0(t)
        p.A1 = h1h + (size_t)(t & 1) * hElems;        p.B1 = Wh1T;
        p.biasP = bP1;
        p.c = c1;
        p.outh = h1h + (size_t)((t & 1) ^ 1) * hElems;
        p.seOut = (t == kL - 1) ? se : nullptr;
        return p;
    };
    // t=0, layer 0: GEMM is zero (h0=0) -> pure gather+gates; writes buffer 1
    lstm0_init_kernel<<<kM * kH / 256, 256>>>(data, kL, G0h, bP0,
                                              c0, h0h + hElems);
    {   // t=0, layer 1: h1=0 -> drop the Wh1 pair; merged with L0(1)
        LstmParams l10 = L1(0);
        l10.nPairs = 1;
        mma_lstm2<<<dim3(k4H / 64, kM / 128, 2), 256, GEMM_SMEM>>>(l10, L0(1));
    }
    for (int t = 1; t < kL - 1; t++)
        mma_lstm2<<<dim3(k4H / 64, kM / 128, 2), 256, GEMM_SMEM>>>(L1(t), L0(t + 1));
    mma_lstm1<<<dim3(k4H / 64, kM / 128), 256, GEMM_SMEM>>>(L1(kL - 1));
    // final h1 fp16 in buffer 0 (t=7 writes wb=0); se fp32 also written

    for (int step = 0; step < kMaxSteps; step++) {
        int cur = step & 1, nxt = cur ^ 1;
        // keys (fp16) = se @ Wk + bk, fused partial ak/aq dots into buf[cur]
        mma_gemm<<<dim3(kH / 64, kM / 128), 256, GEMM_SMEM>>>(
            kM, kH, h1h, WkT, bk, nullptr, keysh, steps, step, Wa,
            ak[cur], aq[cur]);
        // gather reads buf[cur], zeroes buf[nxt] for the next step
        node_gather_kernel<<<kM / 8, 256>>>(src, et, steps, step, ba,
                                            edge_table, keysh,
                                            ak[cur], aq[cur], ak[nxt], aq[nxt],
                                            se, h1h);
        // h1h (buffer 0) holds updated se fp16 for next keys GEMM
    }

    final_kernel<<<kB, 256>>>(se, exit_index, Wo, bo, out);
}

// round 17
// speedup vs baseline: 1.0576x; 1.0108x over previous
#include <cuda_runtime.h>
#include <cuda_fp16.h>
#include <math.h>
#include <stdint.h>

namespace {
constexpr int kB = 8, kN = 4096, kL = 8, kE = 16384, kH = 256;
constexpr int kV = 32000, kOV = 512, kMaxSteps = 6;
constexpr int kM = kB * kN;        // 32768
constexpr int k4H = 4 * kH;        // 1024
constexpr int kET = kB * kE;       // 131072 total edges
constexpr int STAGES = 4;
constexpr int TILE_A = 128 * 80;   // 10240
constexpr int TILE_BB = 64 * 80;   // 5120
constexpr int STAGE_B = TILE_A + TILE_BB;              // 15360
constexpr int GEMM_SMEM = STAGES * STAGE_B;            // 61440 -> 3 CTAs/SM
constexpr int kEmbBlocks = kV * kH / 4 / 256;          // 8000
}

// ---------------- scratch ---------------------------------------------------
__device__ __half g_G0h[(size_t)kV * k4H];        // embed @ Wi0, fp16, gate-permuted
__device__ __half g_c0[kM * kH], g_c1[kM * kH];
__device__ __half g_h0h[2][kM * kH];
__device__ __half g_h1h[2][kM * kH];              // buffer 0 doubles as se fp16
__device__ float g_se[kM * kH];
__device__ __half g_embh[(size_t)kV * kH];
__device__ __half g_Wi0T[k4H * kH], g_Wh0T[k4H * kH];
__device__ __half g_Wi1T[k4H * kH], g_Wh1T[k4H * kH];
__device__ __half g_WkT[kH * kH];
__device__ float g_bP0[k4H], g_bP1[k4H];
__device__ __half g_keysh[kM * kH];
__device__ float g_akq[4][kM];                    // ping-pong: ak0,aq0,ak1,aq1
__device__ float g_ae[8];
// CSR by destination node (built once per launch; topology is static)
// g_epack holds src | (et<<24) in CSR order (no eidx indirection)
__device__ int g_cnt[kM], g_cur[kM], g_off[kM + 1], g_epack[kET];

// ---------------- PTX helpers ----------------------------------------------
__device__ __forceinline__ uint32_t smem_u32(const void* p) {
    uint32_t a;
    asm("{ .reg .u64 t; cvta.to.shared.u64 t, %1; cvt.u32.u64 %0, t; }"
        : "=r"(a) : "l"(p));
    return a;
}
__device__ __forceinline__ void cpasync16(uint32_t dst, const void* src) {
    asm volatile("cp.async.cg.shared.global [%0], [%1], 16;"
                 :: "r"(dst), "l"(src) : "memory");
}
__device__ __forceinline__ void cp_commit() {
    asm volatile("cp.async.commit_group;" ::: "memory");
}
template <int N>
__device__ __forceinline__ void cp_wait() {
    asm volatile("cp.async.wait_group %0;" :: "n"(N) : "memory");
}
__device__ __forceinline__ void ldsm4(uint32_t* r, uint32_t a) {
    asm volatile("ldmatrix.sync.aligned.m8n8.x4.shared.b16 {%0,%1,%2,%3}, [%4];"
                 : "=r"(r[0]), "=r"(r[1]), "=r"(r[2]), "=r"(r[3]) : "r"(a));
}
__device__ __forceinline__ void mma16816(float* d, const uint32_t* a, const uint32_t* b) {
    asm volatile(
        "mma.sync.aligned.m16n8k16.row.col.f32.f16.f16.f32 "
        "{%0,%1,%2,%3}, {%4,%5,%6,%7}, {%8,%9}, {%0,%1,%2,%3};"
        : "+f"(d[0]), "+f"(d[1]), "+f"(d[2]), "+f"(d[3])
        : "r"(a[0]), "r"(a[1]), "r"(a[2]), "r"(a[3]), "r"(b[0]), "r"(b[1]));
}
__device__ __forceinline__ float sigm(float x) { return 1.f / (1.f + expf(-x)); }

// ---------------- shared GEMM mainloop pieces --------------------------------
// CTA tile 128(M) x 64(N), K-chunk 32, 4 stages (round-13 proven config).
#define GEMM_PROLOGUE                                                            \
    extern __shared__ __align__(128) char smem[];                               \
    const int tid = threadIdx.x, wid = tid >> 5, lane = tid & 31;               \
    const int mBase = blockIdx.y * 128, nBase = blockIdx.x * 64;                \
    const int wM = (wid & 3) * 32, wN = (wid >> 2) * 32;                        \
    const uint32_t sbase = smem_u32(smem);                                      \
    float acc[2][4][4];                                                         \
    _Pragma("unroll") for (int i = 0; i < 2; i++)                               \
    _Pragma("unroll") for (int j = 0; j < 4; j++)                               \
    _Pragma("unroll") for (int k = 0; k < 4; k++) acc[i][j][k] = 0.f;

__device__ __forceinline__ void load_tiles(uint32_t sbase, int buf, int tid,
        const __half* __restrict__ Ap, const __half* __restrict__ Bp,
        int mBase, int nBase, int kt) {
    const uint32_t sA = sbase + (uint32_t)buf * STAGE_B;
    const uint32_t sB = sA + TILE_A;
#pragma unroll
    for (int i = 0; i < 2; i++) {
        int idx = i * 256 + tid;
        int r = idx >> 2, c4 = idx & 3;
        cpasync16(sA + r * 80 + c4 * 16,
                  Ap + (size_t)(mBase + r) * 256 + kt + c4 * 8);
    }
    {
        int r = tid >> 2, c4 = tid & 3;
        cpasync16(sB + r * 80 + c4 * 16,
                  Bp + (size_t)(nBase + r) * 256 + kt + c4 * 8);
    }
    cp_commit();
}

__device__ __forceinline__ void compute_tiles(uint32_t sbase, int buf,
        int wM, int wN, int lane, float acc[2][4][4]) {
    const uint32_t sA = sbase + (uint32_t)buf * STAGE_B;
    const uint32_t sB = sA + TILE_A;
#pragma unroll
    for (int ks = 0; ks < 2; ks++) {
        uint32_t a[2][4];
#pragma unroll
        for (int mt = 0; mt < 2; mt++) {
            int row = wM + mt * 16 + (lane & 15);
            ldsm4(a[mt], sA + row * 80 + ((lane >> 4) * 16) + ks * 32);
        }
#pragma unroll
        for (int nt2 = 0; nt2 < 2; nt2++) {
            uint32_t b[4];
            int nrow = wN + nt2 * 16 + (lane & 7) + ((lane >> 4) << 3);
            ldsm4(b, sB + nrow * 80 + (((lane >> 3) & 1) * 16) + ks * 32);
            mma16816(acc[0][nt2 * 2 + 0], a[0], b + 0);
            mma16816(acc[0][nt2 * 2 + 1], a[0], b + 2);
            mma16816(acc[1][nt2 * 2 + 0], a[1], b + 0);
            mma16816(acc[1][nt2 * 2 + 1], a[1], b + 2);
        }
    }
}

#define GEMM_MAINLOOP(NCHUNKS, SRCS)                                            \
    {                                                                            \
        const __half *Ap_, *Bp_; int kt_;                                        \
        _Pragma("unroll") for (int s = 0; s < STAGES - 1; s++) {                 \
            if (s < (NCHUNKS)) { SRCS(s, Ap_, Bp_, kt_);                         \
                load_tiles(sbase, s, tid, Ap_, Bp_, mBase, nBase, kt_); }        \
            else cp_commit();                                                    \
        }                                                                        \
        for (int c = 0; c < (NCHUNKS); ++c) {                                   \
            cp_wait<STAGES - 2>();                                               \
            __syncthreads();                                                     \
            int pre = c + STAGES - 1;                                            \
            if (pre < (NCHUNKS)) { SRCS(pre, Ap_, Bp_, kt_);                     \
                load_tiles(sbase, pre & (STAGES - 1), tid, Ap_, Bp_,             \
                           mBase, nBase, kt_); }                                 \
            else cp_commit();                                                    \
            compute_tiles(sbase, c & (STAGES - 1), wM, wN, lane, acc);           \
        }                                                                        \
    }

// ---------------- generic 1-pass fp16 GEMM (G0 precompute, keys) -------------
__global__ void __launch_bounds__(256, 3) mma_gemm(
    int M, int NTotal,
    const __half* __restrict__ A, const __half* __restrict__ B,
    const float* __restrict__ bias, float* __restrict__ C,
    __half* __restrict__ Ch,
    const int* __restrict__ steps, int step, const float* __restrict__ Wa,
    float* __restrict__ akOut, float* __restrict__ aqOut)
{
    if (steps && step >= steps[(blockIdx.y * 128) / kN]) return;
    GEMM_PROLOGUE
#define SRCS_PLAIN(c, Ap, Bp, kt) { Ap = A; Bp = B; kt = (c) * 32; }
    GEMM_MAINLOOP(8, SRCS_PLAIN)
#undef SRCS_PLAIN

#pragma unroll
    for (int mt = 0; mt < 2; mt++) {
        int r0 = mBase + wM + mt * 16 + (lane >> 2);
        int r1 = r0 + 8;
        float ak0 = 0.f, aq0 = 0.f, ak1 = 0.f, aq1 = 0.f;
#pragma unroll
        for (int nt = 0; nt < 4; nt++) {
            int n = nBase + wN + nt * 8 + (lane & 3) * 2;
            float2 v0 = make_float2(acc[mt][nt][0], acc[mt][nt][1]);
            float2 v1 = make_float2(acc[mt][nt][2], acc[mt][nt][3]);
            if (bias) {
                float2 bv = *(const float2*)(bias + n);
                v0.x += bv.x; v0.y += bv.y; v1.x += bv.x; v1.y += bv.y;
            }
            if (Ch) {
                *(__half2*)(Ch + (size_t)r0 * NTotal + n) =
                    __halves2half2(__float2half(v0.x), __float2half(v0.y));
                *(__half2*)(Ch + (size_t)r1 * NTotal + n) =
                    __halves2half2(__float2half(v1.x), __float2half(v1.y));
            }
            if (C) {
                *(float2*)(C + (size_t)r0 * NTotal + n) = v0;
                *(float2*)(C + (size_t)r1 * NTotal + n) = v1;
            }
            if (Wa) {
                float2 w1 = *(const float2*)(Wa + n);
                float2 w2 = *(const float2*)(Wa + kH + n);
                ak0 += v0.x * w1.x + v0.y * w1.y;
                aq0 += v0.x * w2.x + v0.y * w2.y;
                ak1 += v1.x * w1.x + v1.y * w1.y;
                aq1 += v1.x * w2.x + v1.y * w2.y;
            }
        }
        if (Wa) {
#pragma unroll
            for (int o = 1; o <= 2; o <<= 1) {
                ak0 += __shfl_xor_sync(0xffffffffu, ak0, o);
                aq0 += __shfl_xor_sync(0xffffffffu, aq0, o);
                ak1 += __shfl_xor_sync(0xffffffffu, ak1, o);
                aq1 += __shfl_xor_sync(0xffffffffu, aq1, o);
            }
            if ((lane & 3) == 0) {
                atomicAdd(&akOut[r0], ak0);
                atomicAdd(&aqOut[r0], aq0);
                atomicAdd(&akOut[r1], ak1);
                atomicAdd(&aqOut[r1], aq1);
            }
        }
    }
}

// ---------------- fused LSTM GEMM + gates (1-pass fp16) -----------------------
struct LstmParams {
    int nPairs;
    const __half* A0; const __half* B0;
    const __half* A1; const __half* B1;
    const float* biasP;
    const __half* G0h; const int* tokIdx; int tokStride;
    __half* c; __half* outh; float* seOut;
};

__device__ __forceinline__ void lstm_body(const LstmParams& P)
{
    GEMM_PROLOGUE
    const int nChunks = P.nPairs * 8;
#define SRCS_LSTM(cc, Ap, Bp, kt) { int pair_ = (cc) >> 3;                      \
        kt = ((cc) & 7) * 32;                                                    \
        Ap = pair_ ? P.A1 : P.A0; Bp = pair_ ? P.B1 : P.B0; }
    GEMM_MAINLOOP(nChunks, SRCS_LSTM)
#undef SRCS_LSTM

#pragma unroll
    for (int mt = 0; mt < 2; mt++) {
        int r0 = mBase + wM + mt * 16 + (lane >> 2);
        int r1 = r0 + 8;
        const __half *g0 = nullptr, *g1 = nullptr;
        if (P.G0h) {
            g0 = P.G0h + (size_t)P.tokIdx[(size_t)r0 * P.tokStride] * k4H;
            g1 = P.G0h + (size_t)P.tokIdx[(size_t)r1 * P.tokStride] * k4H;
        }
#pragma unroll
        for (int nt = 0; nt < 4; nt++) {
            int n = nBase + wN + nt * 8 + (lane & 3) * 2;
            float z0 = acc[mt][nt][0] + P.biasP[n];
            float z1 = acc[mt][nt][1] + P.biasP[n + 1];
            float z2 = acc[mt][nt][2] + P.biasP[n];
            float z3 = acc[mt][nt][3] + P.biasP[n + 1];
            if (g0) {
                __half2 a0 = *(const __half2*)(g0 + n);
                __half2 a1 = *(const __half2*)(g1 + n);
                z0 += __half2float(a0.x); z1 += __half2float(a0.y);
                z2 += __half2float(a1.x); z3 += __half2float(a1.y);
            }
            float e0 = __shfl_xor_sync(0xffffffffu, z0, 1);
            float e1 = __shfl_xor_sync(0xffffffffu, z1, 1);
            float e2 = __shfl_xor_sync(0xffffffffu, z2, 1);
            float e3 = __shfl_xor_sync(0xffffffffu, z3, 1);
            bool evn = (lane & 1) == 0;
            int row = evn ? r0 : r1;
            float zi = evn ? z0 : e2;
            float zf = evn ? z1 : e3;
            float zg = evn ? e0 : z2;
            float zo = evn ? e1 : z3;
            int uG = ((nBase + wN + nt * 8) >> 2) + ((lane & 3) >> 1);
            size_t idx = (size_t)row * kH + uG;
            float cn = sigm(zf) * __half2float(P.c[idx]) + sigm(zi) * tanhf(zg);
            P.c[idx] = __float2half(cn);
            float hn = sigm(zo) * tanhf(cn);
            P.outh[idx] = __float2half(hn);
            if (P.seOut) P.seOut[idx] = hn;
        }
    }
}

__global__ void __launch_bounds__(256, 3) mma_lstm1(LstmParams pa)
{
    lstm_body(pa);
}
// merged wavefront: z=0 runs layer1(t), z=1 runs layer0(t+1) — independent
__global__ void __launch_bounds__(256, 3) mma_lstm2(LstmParams pa, LstmParams pb)
{
    lstm_body(blockIdx.z ? pb : pa);
}

// ---------------- t=0 layer-0 special case: h0=0 -> z = G0[token] + bias ------
__global__ void __launch_bounds__(256) lstm0_init_kernel(
    const int* __restrict__ tokIdx, int tokStride,
    const __half* __restrict__ G0h, const float* __restrict__ bP0,
    __half* __restrict__ c, __half* __restrict__ outh)
{
    int idx = blockIdx.x * 256 + threadIdx.x;     // m*kH + u
    int m = idx >> 8, u = idx & 255;
    int tok = tokIdx[(size_t)m * tokStride];
    uint2 gv = *(const uint2*)(G0h + (size_t)tok * k4H + u * 4);
    __half2 ga = *(__half2*)&gv.x;
    __half2 gb = *(__half2*)&gv.y;
    const float4 bv = *(const float4*)(bP0 + u * 4);
    float zi = __half2float(ga.x) + bv.x;
    float zg = __half2float(gb.x) + bv.z;
    float zo = __half2float(gb.y) + bv.w;
    float cn = sigm(zi) * tanhf(zg);              // f-term vanishes (c=0)
    c[idx] = __float2half(cn);
    outh[idx] = __float2half(sigm(zo) * tanhf(cn));
}

// ---------------- consolidated prep: weights + bias + ae + csr-zero + embed ---
__global__ void __launch_bounds__(256) prep_kernel(
    const float* __restrict__ Wi0, const float* __restrict__ Wh0,
    const float* __restrict__ Wi1, const float* __restrict__ Wh1,
    const float* __restrict__ Wk,
    const float* __restrict__ b0, const float* __restrict__ b1,
    const float* __restrict__ edge_table, const float* __restrict__ Wa,
    const float4* __restrict__ embed,
    __half* __restrict__ Wi0T, __half* __restrict__ Wh0T,
    __half* __restrict__ Wi1T, __half* __restrict__ Wh1T,
    __half* __restrict__ WkT, float* __restrict__ bP0, float* __restrict__ bP1,
    __half2* __restrict__ embh)
{
    int blk = blockIdx.x;
    if (blk < 512) {
        const float* W; __half* T;
        switch (blk >> 7) {
            case 0: W = Wi0; T = Wi0T; break;
            case 1: W = Wh0; T = Wh0T; break;
            case 2: W = Wi1; T = Wi1T; break;
            default: W = Wh1; T = Wh1T;
        }
        int n = (blk & 127) * 8 + (threadIdx.x >> 5);
        int lane = threadIdx.x & 31;
        int col = (n & 3) * kH + (n >> 2);
        for (int kk = lane; kk < kH; kk += 32)
            T[(size_t)n * kH + kk] = __float2half(W[(size_t)kk * k4H + col]);
    } else if (blk < 544) {
        int n = (blk - 512) * 8 + (threadIdx.x >> 5);
        int lane = threadIdx.x & 31;
        for (int kk = lane; kk < kH; kk += 32)
            WkT[(size_t)n * kH + kk] = __float2half(Wk[(size_t)kk * kH + n]);
    } else if (blk < 552) {
        int i = blk - 544;                       // 0..7
        const float* b = (i < 4) ? b0 : b1;
        float* bP = (i < 4) ? bP0 : bP1;
        int n = (i & 3) * 256 + threadIdx.x;
        bP[n] = b[(n & 3) * kH + (n >> 2)];
    } else if (blk == 552) {
        // ae[w] = edge_table[w] . Wa[:256]
        int w = threadIdx.x >> 5, lane = threadIdx.x & 31;
        if (w >= 6) return;
        float s = 0.f;
        for (int hh = lane; hh < kH; hh += 32)
            s += edge_table[w * kH + hh] * Wa[hh];
#pragma unroll
        for (int o = 16; o; o >>= 1) s += __shfl_down_sync(0xffffffffu, s, o);
        if (!lane) g_ae[w] = s;
    } else if (blk < 553 + kM / 256) {
        int i = (blk - 553) * 256 + threadIdx.x;
        g_cnt[i] = 0;
        g_cur[i] = 0;
    } else {
        int i = (blk - 553 - kM / 256) * 256 + threadIdx.x;
        float4 v = embed[i];
        embh[i * 2 + 0] = __halves2half2(__float2half(v.x), __float2half(v.y));
        embh[i * 2 + 1] = __halves2half2(__float2half(v.z), __float2half(v.w));
    }
}

// ---------------- CSR build (once per launch; topology static) ----------------
__global__ void csr_count_kernel(const int* __restrict__ dst)
{
    int e = blockIdx.x * 256 + threadIdx.x;
    int node = (e / kE) * kN + dst[e];
    atomicAdd(&g_cnt[node], 1);
}
__global__ void __launch_bounds__(1024) csr_scan_kernel()
{
    __shared__ int sh[1024];
    __shared__ int carry;
    int tid = threadIdx.x;
    if (tid == 0) carry = 0;
    __syncthreads();
    for (int chunk = 0; chunk < kM / 1024; chunk++) {
        int i = chunk * 1024 + tid;
        int v = g_cnt[i];
        sh[tid] = v;
        __syncthreads();
        for (int o = 1; o < 1024; o <<= 1) {
            int t = (tid >= o) ? sh[tid - o] : 0;
            __syncthreads();
            sh[tid] += t;
            __syncthreads();
        }
        g_off[i] = carry + sh[tid] - v;     // exclusive
        __syncthreads();
        if (tid == 1023) carry += sh[1023];
        __syncthreads();
    }
    if (tid == 0) g_off[kM] = carry;
}
// stores packed src|et<<24 directly in CSR order (no second indirection)
__global__ void csr_scatter_kernel(const int* __restrict__ dst,
                                   const int* __restrict__ src,
                                   const int* __restrict__ et)
{
    int e = blockIdx.x * 256 + threadIdx.x;
    int node = (e / kE) * kN + dst[e];
    int pos = g_off[node] + atomicAdd(&g_cur[node], 1);
    g_epack[pos] = src[e] | (et[e] << 24);
}

// gather with fused edge scoring; zeroes NEXT step's ak/aq buffers (ping-pong)
__global__ void __launch_bounds__(256) node_gather_kernel(
    const int* __restrict__ steps, int step, const float* __restrict__ ba,
    const float* __restrict__ edge_table,
    const __half* __restrict__ keysh,
    const float* __restrict__ akCur, const float* __restrict__ aqCur,
    float* __restrict__ akNext, float* __restrict__ aqNext,
    float* __restrict__ se, __half* __restrict__ seh)
{
    int node = blockIdx.x * 8 + (threadIdx.x >> 5);
    int lane = threadIdx.x & 31;
    int b = node / kN;
    if (step >= steps[b]) return;
    int lo = g_off[node], hi = g_off[node + 1];
    float acc[8] = {0, 0, 0, 0, 0, 0, 0, 0};
    float sum_ex = 0.f;
    int base = b * kN;
    float aq_ba = aqCur[node] + ba[0];
    for (int i = lo; i < hi; i++) {
        int pk = g_epack[i];
        int s = pk & 0xFFFFFF, t = pk >> 24;
        float lg = akCur[base + s] + g_ae[t] + aq_ba;
        lg = fmaxf(0.2f * lg, lg);
        float ex = expf(lg);
        sum_ex += ex;
        const __half2* kr = (const __half2*)(keysh + (size_t)(base + s) * kH + lane * 8);
        const float4* er = (const float4*)(edge_table + t * kH + lane * 8);
        __half2 k0 = kr[0], k1 = kr[1], k2 = kr[2], k3 = kr[3];
        float4 e0 = er[0], e1 = er[1];
        acc[0] += (__half2float(k0.x) + e0.x) * ex;
        acc[1] += (__half2float(k0.y) + e0.y) * ex;
        acc[2] += (__half2float(k1.x) + e0.z) * ex;
        acc[3] += (__half2float(k1.y) + e0.w) * ex;
        acc[4] += (__half2float(k2.x) + e1.x) * ex;
        acc[5] += (__half2float(k2.y) + e1.y) * ex;
        acc[6] += (__half2float(k3.x) + e1.z) * ex;
        acc[7] += (__half2float(k3.y) + e1.w) * ex;
    }
    float inv = (hi > lo) ? (1.f / sum_ex) : 0.f;
    float4 o0, o1;
    o0.x = acc[0] * inv; o0.y = acc[1] * inv; o0.z = acc[2] * inv; o0.w = acc[3] * inv;
    o1.x = acc[4] * inv; o1.y = acc[5] * inv; o1.z = acc[6] * inv; o1.w = acc[7] * inv;
    float4* srow = (float4*)(se + (size_t)node * kH + lane * 8);
    srow[0] = o0;
    srow[1] = o1;
    __half2* hrow = (__half2*)(seh + (size_t)node * kH + lane * 8);
    hrow[0] = __halves2half2(__float2half(o0.x), __float2half(o0.y));
    hrow[1] = __halves2half2(__float2half(o0.z), __float2half(o0.w));
    hrow[2] = __halves2half2(__float2half(o1.x), __float2half(o1.y));
    hrow[3] = __halves2half2(__float2half(o1.z), __float2half(o1.w));
    if (lane == 0) { akNext[node] = 0.f; aqNext[node] = 0.f; }
}

// ---------------- final gather + dense ---------------------------------------
__global__ void __launch_bounds__(256) final_kernel(
    const float* __restrict__ se, const int* __restrict__ exit_index,
    const float* __restrict__ Wo, const float* __restrict__ bo,
    float* __restrict__ out)
{
    __shared__ float fin[kH];
    int b = blockIdx.x, tid = threadIdx.x;
    const float* row = se + ((size_t)b * kN + exit_index[b]) * kH;
    if (tid < kH) fin[tid] = row[tid];
    __syncthreads();
    for (int j = tid; j < kOV; j += 256) {
        float s = bo[j];
        for (int hh = 0; hh < kH; hh++) s += fin[hh] * Wo[(size_t)hh * kOV + j];
        out[b * kOV + j] = s;
    }
}

// ---------------- driver ------------------------------------------------------
extern "C" void kernel_launch(void* const* d_in, const int* in_sizes, int n_in,
                              void* d_out, int out_size)
{
    const int*   data       = (const int*)d_in[0];
    const int*   src        = (const int*)d_in[1];
    const int*   dst        = (const int*)d_in[2];
    const int*   et         = (const int*)d_in[3];
    const int*   steps      = (const int*)d_in[4];
    const int*   exit_index = (const int*)d_in[5];
    const float* embed      = (const float*)d_in[6];
    const float* Wi0        = (const float*)d_in[7];
    const float* Wh0        = (const float*)d_in[8];
    const float* b0         = (const float*)d_in[9];
    const float* Wi1        = (const float*)d_in[10];
    const float* Wh1        = (const float*)d_in[11];
    const float* b1         = (const float*)d_in[12];
    const float* Wk         = (const float*)d_in[13];
    const float* bk         = (const float*)d_in[14];
    const float* Wa         = (const float*)d_in[15];
    const float* ba         = (const float*)d_in[16];
    const float* edge_table = (const float*)d_in[17];
    const float* Wo         = (const float*)d_in[18];
    const float* bo         = (const float*)d_in[19];
    float* out = (float*)d_out;

    float *se, *bP0, *bP1, *akq;
    __half *G0h, *c0, *c1, *h0h, *h1h, *embh, *keysh;
    __half *Wi0T, *Wh0T, *Wi1T, *Wh1T, *WkT;
    cudaGetSymbolAddress((void**)&G0h,   g_G0h);
    cudaGetSymbolAddress((void**)&c0,    g_c0);
    cudaGetSymbolAddress((void**)&c1,    g_c1);
    cudaGetSymbolAddress((void**)&se,    g_se);
    cudaGetSymbolAddress((void**)&keysh, g_keysh);
    cudaGetSymbolAddress((void**)&h0h,   g_h0h);
    cudaGetSymbolAddress((void**)&h1h,   g_h1h);
    cudaGetSymbolAddress((void**)&embh,  g_embh);
    cudaGetSymbolAddress((void**)&Wi0T,  g_Wi0T);
    cudaGetSymbolAddress((void**)&Wh0T,  g_Wh0T);
    cudaGetSymbolAddress((void**)&Wi1T,  g_Wi1T);
    cudaGetSymbolAddress((void**)&Wh1T,  g_Wh1T);
    cudaGetSymbolAddress((void**)&WkT,   g_WkT);
    cudaGetSymbolAddress((void**)&bP0,   g_bP0);
    cudaGetSymbolAddress((void**)&bP1,   g_bP1);
    cudaGetSymbolAddress((void**)&akq,   g_akq);
    float* ak[2] = { akq,      akq + 2 * kM };
    float* aq[2] = { akq + kM, akq + 3 * kM };

    cudaFuncSetAttribute(mma_gemm, cudaFuncAttributeMaxDynamicSharedMemorySize, GEMM_SMEM);
    cudaFuncSetAttribute(mma_lstm1, cudaFuncAttributeMaxDynamicSharedMemorySize, GEMM_SMEM);
    cudaFuncSetAttribute(mma_lstm2, cudaFuncAttributeMaxDynamicSharedMemorySize, GEMM_SMEM);

    const size_t hElems = (size_t)kM * kH;
    cudaMemsetAsync(c1, 0, hElems * 2);   // L1(0) epilogue reads c1
    cudaMemsetAsync(akq, 0, 4 * kM * sizeof(float));  // both ak/aq buffers

    // one prep launch: weight transposes, biases, ae dots, csr-zero, embed->fp16
    prep_kernel<<<553 + kM / 256 + kEmbBlocks, 256>>>(
        Wi0, Wh0, Wi1, Wh1, Wk, b0, b1, edge_table, Wa,
        (const float4*)embed,
        Wi0T, Wh0T, Wi1T, Wh1T, WkT, bP0, bP1, (__half2*)embh);

    // CSR build (static topology: once per launch)
    csr_count_kernel<<<kET / 256, 256>>>(dst);
    csr_scan_kernel<<<1, 1024>>>();
    csr_scatter_kernel<<<kET / 256, 256>>>(dst, src, et);

    // G0 = embed @ Wi0 (gate-permuted, fp16)  [32000, 1024]
    mma_gemm<<<dim3(k4H / 64, kV / 128), 256, GEMM_SMEM>>>(
        kV, k4H, embh, Wi0T, nullptr, nullptr, G0h, nullptr, 0,
        nullptr, nullptr, nullptr);

    // ---- LSTM wavefront ----
    auto L0 = [&](int t) {
        LstmParams p{};
        p.nPairs = 1;
        p.A0 = h0h + (size_t)(t & 1) * hElems;  p.B0 = Wh0T;
        p.biasP = bP0;
        p.G0h = G0h; p.tokIdx = data + t; p.tokStride = kL;
        p.c = c0;
        p.outh = h0h + (size_t)((t & 1) ^ 1) * hElems;
        p.seOut = nullptr;
        return p;
    };
    auto L1 = [&](int t) {
        LstmParams p{};
        p.nPairs = 2;
        p.A0 = h0h + (size_t)((t & 1) ^ 1) * hElems;  p.B0 = Wi1T;  // h0(t)
        p.A1 = h1h + (size_t)(t & 1) * hElems;        p.B1 = Wh1T;
        p.biasP = bP1;
        p.c = c1;
        p.outh = h1h + (size_t)((t & 1) ^ 1) * hElems;
        p.seOut = (t == kL - 1) ? se : nullptr;
        return p;
    };
    // t=0, layer 0: GEMM is zero (h0=0) -> pure gather+gates; writes buffer 1
    lstm0_init_kernel<<<kM * kH / 256, 256>>>(data, kL, G0h, bP0,
                                              c0, h0h + hElems);
    {   // t=0, layer 1: h1=0 -> drop the Wh1 pair; merged with L0(1)
        LstmParams l10 = L1(0);
        l10.nPairs = 1;
        mma_lstm2<<<dim3(k4H / 64, kM / 128, 2), 256, GEMM_SMEM>>>(l10, L0(1));
    }
    for (int t = 1; t < kL - 1; t++)
        mma_lstm2<<<dim3(k4H / 64, kM / 128, 2), 256, GEMM_SMEM>>>(L1(t), L0(t + 1));
    mma_lstm1<<<dim3(k4H / 64, kM / 128), 256, GEMM_SMEM>>>(L1(kL - 1));
    // final h1 fp16 in buffer 0 (t=7 writes wb=0); se fp32 also written

    for (int step = 0; step < kMaxSteps; step++) {
        int cur = step & 1, nxt = cur ^ 1;
        // keys (fp16) = se @ Wk + bk, fused partial ak/aq dots into buf[cur]
        mma_gemm<<<dim3(kH / 64, kM / 128), 256, GEMM_SMEM>>>(
            kM, kH, h1h, WkT, bk, nullptr, keysh, steps, step, Wa,
            ak[cur], aq[cur]);
        // gather reads buf[cur], zeroes buf[nxt] for the next step
        node_gather_kernel<<<kM / 8, 256>>>(steps, step, ba,
                                            edge_table, keysh,
                                            ak[cur], aq[cur], ak[nxt], aq[nxt],
                                            se, h1h);
        // h1h (buffer 0) holds updated se fp16 for next keys GEMM
    }

    final_kernel<<<kB, 256>>>(se, exit_index, Wo, bo, out);
}